// round 13
// baseline (speedup 1.0000x reference)
#include <cuda_runtime.h>
#include <cuda_fp16.h>
#include <math.h>

#define Nn 30000
#define NN0 18000
#define NN1 12000
#define Rr 5
#define Ee 600000
#define Hh 128
#define Cc 8
#define OFF_X (Nn*Cc)            /* 240000   */
#define OFF_U (OFF_X + Nn*Hh)    /* 4080000  */

#define GRID 592                  /* 148 SMs x 4 co-resident blocks */
#define BLK  256
#define WPB  (BLK/32)
#define NWARPS (GRID*WPB)

#define NB0 ((NN0+63)/64)         /* 282 */
#define NB1 ((NN1+63)/64)         /* 188 */

#define ASP 68                    /* k-major A tile pad: 272B rows, 16B aligned */

// ---------------- device scratch (static, no allocation) ----------------
__device__ float  g_h [Nn*Hh];
__device__ float  g_xa[Nn*Hh];                 // fp32 x, updated in place
__device__ __half g_xh[Nn*Hh];                 // fp16 mirror of current x
__device__ __half g_msgh[(size_t)Rr*Nn*Hh];    // per-relation messages fp16
__device__ int    g_degi[Rr*Nn];
__device__ int    g_cnt[Nn];
__device__ int    g_rowptr[Nn+1];
__device__ int    g_cur2[Rr*Nn];
__device__ int    g_bsums[64];
__device__ int2   g_csr[Ee];                   // (dst, edinv-as-int) packed
__device__ double g_node[Rr];
__device__ double g_edge[Rr];
__device__ float  g_u[Rr];
__device__ float  g_clt;
__device__ int    g_act;
__device__ int    g_still;
__device__ unsigned g_bcount;
__device__ volatile unsigned g_bsense;

__device__ __forceinline__ float wsum(float v){
    #pragma unroll
    for (int o = 16; o; o >>= 1) v += __shfl_xor_sync(0xffffffffu, v, o);
    return v;
}
__device__ __forceinline__ float n2n(float v){
    if (isnan(v)) return 0.f;
    if (isinf(v)) return v > 0.f ? 3.4028234663852886e38f : -3.4028234663852886e38f;
    return v;
}

// ---- packed f32x2 helpers (B300 FFMA2 path, PTX-only) ----
__device__ __forceinline__ unsigned long long f2pack(float x, float y){
    unsigned long long r;
    asm("mov.b64 %0, {%1, %2};" : "=l"(r)
        : "r"(__float_as_uint(x)), "r"(__float_as_uint(y)));
    return r;
}
__device__ __forceinline__ void ffma2(unsigned long long& acc,
                                      unsigned long long a, unsigned long long b){
    asm("fma.rn.f32x2 %0, %1, %2, %0;" : "+l"(acc) : "l"(a), "l"(b));
}
__device__ __forceinline__ float2 f2unpack(unsigned long long p){
    unsigned a, b;
    asm("mov.b64 {%0, %1}, %2;" : "=r"(a), "=r"(b) : "l"(p));
    return make_float2(__uint_as_float(a), __uint_as_float(b));
}

// ---------------- init / graph preprocessing ----------------
__global__ void k_init(){
    int i = blockIdx.x*blockDim.x + threadIdx.x;
    int st = gridDim.x*blockDim.x;
    for (int j = i; j < Rr*Nn; j += st) g_degi[j] = 0;
    for (int j = i; j < Nn;    j += st) g_cnt[j]  = 0;
    if (i < Rr) { g_node[i] = 0.0; g_edge[i] = 0.0; g_u[i] = 0.2f; }
    if (i == 0) { g_act = 1; g_still = 1; g_bcount = 0u; g_bsense = 0u; }
}

__global__ void k_count(const int* __restrict__ src, const int* __restrict__ rel){
    int i = blockIdx.x*blockDim.x + threadIdx.x;
    if (i < Ee) {
        atomicAdd(&g_degi[rel[i]*Nn + src[i]], 1);
        atomicAdd(&g_cnt[src[i]], 1);
    }
}

__global__ void k_scan1(){
    __shared__ int s[1024];
    int i = blockIdx.x*1024 + threadIdx.x;
    int v = (i < Nn) ? g_cnt[i] : 0;
    s[threadIdx.x] = v;
    __syncthreads();
    for (int off = 1; off < 1024; off <<= 1){
        int t = 0;
        if (threadIdx.x >= off) t = s[threadIdx.x - off];
        __syncthreads();
        if (threadIdx.x >= off) s[threadIdx.x] += t;
        __syncthreads();
    }
    if (i < Nn) g_rowptr[i] = s[threadIdx.x] - v;
    if (threadIdx.x == 1023) g_bsums[blockIdx.x] = s[1023];
}

__global__ void k_scan2(int nb){
    if (threadIdx.x == 0){
        int run = 0;
        for (int b = 0; b < nb; b++){ int t = g_bsums[b]; g_bsums[b] = run; run += t; }
    }
}

// fused: finalize rowptr + per-(node,rel) cursors
__global__ void k_scan3c(){
    int i = blockIdx.x*blockDim.x + threadIdx.x;
    if (i < Nn){
        int base = g_rowptr[i] + g_bsums[i >> 10];
        g_rowptr[i] = base;
        #pragma unroll
        for (int r = 0; r < Rr; r++){
            g_cur2[r*Nn + i] = base;
            base += g_degi[r*Nn + i];
        }
    }
    if (i == 0) g_rowptr[Nn] = Ee;
}

__global__ void k_scatter2(const int* __restrict__ src, const int* __restrict__ dst,
                           const int* __restrict__ rel){
    int i = blockIdx.x*blockDim.x + threadIdx.x;
    if (i >= Ee) return;
    int s = src[i], r = rel[i], d = dst[i];
    int pos = atomicAdd(&g_cur2[r*Nn + s], 1);
    int degs = g_degi[r*Nn + s];
    int degd = g_degi[r*Nn + d];
    float ei = (1.f/sqrtf((float)degs)) * (degd > 0 ? 1.f/sqrtf((float)degd) : 0.f);
    int2 pk; pk.x = d; pk.y = __float_as_int(ei);
    g_csr[pos] = pk;
}

// ------- merged typed GEMM (FFMA2 row-paired): [0,NB0) feat0@W0, rest feat1@W1 -------
__global__ void __launch_bounds__(256, 2) k_typed(const float* __restrict__ feat0,
                                                  const float* __restrict__ W0,
                                                  const float* __restrict__ b0,
                                                  const float* __restrict__ feat1,
                                                  const float* __restrict__ W1,
                                                  const float* __restrict__ b1){
    __shared__ float As[16*ASP];   // k-major: As[k][row]
    __shared__ float Bs[16*128];
    const float *A, *W, *bias;
    int lda, nrows, rowbase, K, blk;
    if (blockIdx.x < NB0){
        A = feat0; W = W0; bias = b0; lda = 256; nrows = NN0; rowbase = 0;   K = 256; blk = blockIdx.x;
    } else {
        A = feat1; W = W1; bias = b1; lda = 128; nrows = NN1; rowbase = NN0; K = 128; blk = blockIdx.x - NB0;
    }
    int tid  = threadIdx.x;
    int tcol = tid & 31, trow = tid >> 5;
    int row0 = blk * 64;
    unsigned long long accp[4][4];
    #pragma unroll
    for (int p = 0; p < 4; p++)
        #pragma unroll
        for (int j = 0; j < 4; j++) accp[p][j] = 0ull;

    for (int k0 = 0; k0 < K; k0 += 16){
        #pragma unroll
        for (int i = 0; i < 4; i++){
            int lin = tid + 256*i;
            int r = lin >> 4, k = lin & 15;
            int gr = row0 + r;
            As[k*ASP + r] = (gr < nrows) ? A[(size_t)gr*lda + k0 + k] : 0.f;
        }
        #pragma unroll
        for (int i = 0; i < 8; i++){
            int lin = tid + 256*i;
            int k = lin >> 7, c = lin & 127;
            Bs[k*128+c] = W[(size_t)(k0+k)*128 + c];
        }
        __syncthreads();
        #pragma unroll
        for (int k = 0; k < 16; k++){
            float4 bv = *(const float4*)&Bs[k*128 + tcol*4];
            unsigned long long bd0 = f2pack(bv.x, bv.x);
            unsigned long long bd1 = f2pack(bv.y, bv.y);
            unsigned long long bd2 = f2pack(bv.z, bv.z);
            unsigned long long bd3 = f2pack(bv.w, bv.w);
            float4 a0 = *(const float4*)&As[k*ASP + trow*8];
            float4 a1 = *(const float4*)&As[k*ASP + trow*8 + 4];
            unsigned long long ap[4] = { f2pack(a0.x, a0.y), f2pack(a0.z, a0.w),
                                         f2pack(a1.x, a1.y), f2pack(a1.z, a1.w) };
            #pragma unroll
            for (int p = 0; p < 4; p++){
                ffma2(accp[p][0], ap[p], bd0);
                ffma2(accp[p][1], ap[p], bd1);
                ffma2(accp[p][2], ap[p], bd2);
                ffma2(accp[p][3], ap[p], bd3);
            }
        }
        __syncthreads();
    }
    float4 bv = *(const float4*)&bias[tcol*4];
    #pragma unroll
    for (int p = 0; p < 4; p++){
        float2 u0 = f2unpack(accp[p][0]);
        float2 u1 = f2unpack(accp[p][1]);
        float2 u2 = f2unpack(accp[p][2]);
        float2 u3 = f2unpack(accp[p][3]);
        int gr0 = row0 + trow*8 + 2*p;
        if (gr0 < nrows)
            *(float4*)&g_h[(size_t)(rowbase+gr0)*Hh + tcol*4] =
                make_float4(u0.x+bv.x, u1.x+bv.y, u2.x+bv.z, u3.x+bv.w);
        int gr1 = gr0 + 1;
        if (gr1 < nrows)
            *(float4*)&g_h[(size_t)(rowbase+gr1)*Hh + tcol*4] =
                make_float4(u0.y+bv.x, u1.y+bv.y, u2.y+bv.z, u3.y+bv.w);
    }
}

// ------- stage B (FFMA2): LN(h@Wm1+b)->relu -> @Wm2+b -> standardize -------
__global__ void __launch_bounds__(256, 2) k_mlp2(const float* __restrict__ Wm1, const float* __restrict__ bm1,
                                                 const float* __restrict__ Wm2, const float* __restrict__ bm2){
    __shared__ float As[16*ASP];   // k-major
    __shared__ float Bs[16*128];
    __shared__ float Zs[64*132];   // row-major z
    int tid  = threadIdx.x;
    int tcol = tid & 31, trow = tid >> 5;
    int row0 = blockIdx.x * 64;

    // ---- gemm1: g_h @ Wm1 (row-paired FFMA2) ----
    unsigned long long accp[4][4];
    #pragma unroll
    for (int p = 0; p < 4; p++)
        #pragma unroll
        for (int j = 0; j < 4; j++) accp[p][j] = 0ull;

    for (int k0 = 0; k0 < 128; k0 += 16){
        #pragma unroll
        for (int i = 0; i < 4; i++){
            int lin = tid + 256*i;
            int r = lin >> 4, k = lin & 15;
            int gr = row0 + r;
            As[k*ASP + r] = (gr < Nn) ? g_h[(size_t)gr*Hh + k0 + k] : 0.f;
        }
        #pragma unroll
        for (int i = 0; i < 8; i++){
            int lin = tid + 256*i;
            int k = lin >> 7, c = lin & 127;
            Bs[k*128+c] = Wm1[(size_t)(k0+k)*128 + c];
        }
        __syncthreads();
        #pragma unroll
        for (int k = 0; k < 16; k++){
            float4 bv = *(const float4*)&Bs[k*128 + tcol*4];
            unsigned long long bd0 = f2pack(bv.x, bv.x);
            unsigned long long bd1 = f2pack(bv.y, bv.y);
            unsigned long long bd2 = f2pack(bv.z, bv.z);
            unsigned long long bd3 = f2pack(bv.w, bv.w);
            float4 a0 = *(const float4*)&As[k*ASP + trow*8];
            float4 a1 = *(const float4*)&As[k*ASP + trow*8 + 4];
            unsigned long long ap[4] = { f2pack(a0.x, a0.y), f2pack(a0.z, a0.w),
                                         f2pack(a1.x, a1.y), f2pack(a1.z, a1.w) };
            #pragma unroll
            for (int p = 0; p < 4; p++){
                ffma2(accp[p][0], ap[p], bd0);
                ffma2(accp[p][1], ap[p], bd1);
                ffma2(accp[p][2], ap[p], bd2);
                ffma2(accp[p][3], ap[p], bd3);
            }
        }
        __syncthreads();
    }
    // layernorm + relu -> Zs (row-major)
    {
        float4 b1v = *(const float4*)&bm1[tcol*4];
        #pragma unroll
        for (int p = 0; p < 4; p++){
            float2 u0 = f2unpack(accp[p][0]);
            float2 u1 = f2unpack(accp[p][1]);
            float2 u2 = f2unpack(accp[p][2]);
            float2 u3 = f2unpack(accp[p][3]);
            float rowv[2][4] = { {u0.x+b1v.x, u1.x+b1v.y, u2.x+b1v.z, u3.x+b1v.w},
                                 {u0.y+b1v.x, u1.y+b1v.y, u2.y+b1v.z, u3.y+b1v.w} };
            #pragma unroll
            for (int h = 0; h < 2; h++){
                float v0 = rowv[h][0], v1 = rowv[h][1], v2 = rowv[h][2], v3 = rowv[h][3];
                float s1 = wsum(v0+v1+v2+v3);
                float s2 = wsum(v0*v0+v1*v1+v2*v2+v3*v3);
                float m  = s1 * (1.f/128.f);
                float var = s2 * (1.f/128.f) - m*m;
                float rs = rsqrtf(var + 1e-5f);
                int r = trow*8 + 2*p + h;
                float4 z = make_float4(fmaxf(0.f,(v0-m)*rs), fmaxf(0.f,(v1-m)*rs),
                                       fmaxf(0.f,(v2-m)*rs), fmaxf(0.f,(v3-m)*rs));
                *(float4*)&Zs[r*132 + tcol*4] = z;
            }
        }
    }
    __syncthreads();

    // ---- gemm2: Zs @ Wm2 (col-paired FFMA2; A broadcast from row-major Zs) ----
    unsigned long long acc2p[8][2];
    #pragma unroll
    for (int i = 0; i < 8; i++){ acc2p[i][0] = 0ull; acc2p[i][1] = 0ull; }
    for (int k0 = 0; k0 < 128; k0 += 16){
        #pragma unroll
        for (int i = 0; i < 8; i++){
            int lin = tid + 256*i;
            int k = lin >> 7, c = lin & 127;
            Bs[k*128+c] = Wm2[(size_t)(k0+k)*128 + c];
        }
        __syncthreads();
        #pragma unroll
        for (int k = 0; k < 16; k++){
            float4 bv = *(const float4*)&Bs[k*128 + tcol*4];
            unsigned long long bp0 = f2pack(bv.x, bv.y);
            unsigned long long bp1 = f2pack(bv.z, bv.w);
            #pragma unroll
            for (int ri = 0; ri < 8; ri++){
                float a = Zs[(trow*8+ri)*132 + k0 + k];
                unsigned long long ad = f2pack(a, a);
                ffma2(acc2p[ri][0], ad, bp0);
                ffma2(acc2p[ri][1], ad, bp1);
            }
        }
        __syncthreads();
    }
    // standardize (ddof=1) + nan_to_num -> g_xa + fp16 mirror
    {
        float4 b2v = *(const float4*)&bm2[tcol*4];
        #pragma unroll
        for (int ri = 0; ri < 8; ri++){
            int gr = row0 + trow*8 + ri;
            float2 u0 = f2unpack(acc2p[ri][0]);
            float2 u1 = f2unpack(acc2p[ri][1]);
            float v0 = u0.x+b2v.x, v1 = u0.y+b2v.y;
            float v2 = u1.x+b2v.z, v3 = u1.y+b2v.w;
            float s1 = wsum(v0+v1+v2+v3);
            float s2 = wsum(v0*v0+v1*v1+v2*v2+v3*v3);
            float m  = s1 * (1.f/128.f);
            float varu = (s2 - 128.f*m*m) * (1.f/127.f);
            float sd = sqrtf(varu);
            float o0 = n2n((v0-m)/sd), o1 = n2n((v1-m)/sd);
            float o2 = n2n((v2-m)/sd), o3 = n2n((v3-m)/sd);
            if (gr < Nn){
                *(float4*)&g_xa[(size_t)gr*Hh + tcol*4] = make_float4(o0,o1,o2,o3);
                __half2 p0 = __floats2half2_rn(o0, o1);
                __half2 p1 = __floats2half2_rn(o2, o3);
                uint2 pw;
                pw.x = *(unsigned*)&p0; pw.y = *(unsigned*)&p1;
                *(uint2*)&g_xh[(size_t)gr*Hh + tcol*4] = pw;
            }
        }
    }
}

// ---------------- mirror descent (inside grid barrier; fast-math exp) ----------------
__device__ void dev_md(int kiter){
    float w[Rr]; float l1 = 0.f;
    #pragma unroll
    for (int r = 0; r < Rr; r++){
        double nv = *(volatile double*)&g_node[r];
        double ev = *(volatile double*)&g_edge[r];
        w[r] = (float)((nv - ev) / (double)Nn);
        l1 += fabsf(w[r]);
        *(volatile double*)&g_node[r] = 0.0;
        *(volatile double*)&g_edge[r] = 0.0;
    }
    float clt;
    if (kiter == 0){ clt = l1; *(volatile float*)&g_clt = l1; }
    else clt = *(volatile float*)&g_clt;
    float u[Rr];
    #pragma unroll
    for (int r = 0; r < Rr; r++) u[r] = *(volatile float*)&g_u[r];
    float fi = l1 + 3.0f;          // ratio = 2*L2/L1 = 3
    const float tln = 2.f*1.6094379124341003f;   // 2*log(5)
    float inv_fi2 = 1.f/(fi*fi);
    bool ia = true;
    for (int t = 1; t <= 20 && ia; t++){
        float Tt = sqrtf(tln * inv_fi2 / (float)t);
        float uta[Rr]; float s = 0.f;
        #pragma unroll
        for (int r = 0; r < Rr; r++){ uta[r] = u[r]*__expf(-Tt*(3.f*u[r] + w[r])); s += uta[r]; }
        float is = 1.f/s;
        float dif = 0.f;
        #pragma unroll
        for (int r = 0; r < Rr; r++){
            uta[r] *= is;
            float d = u[r] - uta[r];
            dif += d*d;
            u[r] = uta[r];
        }
        ia = (dif >= 1e-6f);
    }
    #pragma unroll
    for (int r = 0; r < Rr; r++) *(volatile float*)&g_u[r] = u[r];
    int still = (l1 / clt >= 0.3f) ? 1 : 0;
    *(volatile int*)&g_still = still;
    *(volatile int*)&g_act   = still;
}

// ---------------- grid barrier (sense-reversing); last block may run md ----------------
__device__ __forceinline__ void gbar(int run_md, int kiter){
    __syncthreads();
    if (threadIdx.x == 0){
        unsigned s = g_bsense;
        __threadfence();
        unsigned a = atomicAdd(&g_bcount, 1u);
        if (a == (unsigned)(GRID - 1)){
            if (run_md) dev_md(kiter);
            g_bcount = 0u;
            __threadfence();
            g_bsense = s ^ 1u;
        } else {
            while (g_bsense == s) __nanosleep(64);
            __threadfence();
        }
    }
    __syncthreads();
}

// helper: fp16 row fetch (L2-only, cross-SM coherent) -> 4 floats
__device__ __forceinline__ void ld_row_cg(const __half* __restrict__ xh, int node, int lane,
                                          float& a, float& b, float& c, float& d){
    unsigned long long rv = __ldcg((const unsigned long long*)(xh + (size_t)node*Hh + lane*4));
    unsigned lo = (unsigned)rv, hi = (unsigned)(rv >> 32);
    float2 f0 = __half22float2(*(__half2*)&lo);
    float2 f1 = __half22float2(*(__half2*)&hi);
    a = f0.x; b = f0.y; c = f1.x; d = f1.y;
}

// ---------------- persistent loop: 8 x (gather -> md -> combine) + final output ----------------
__global__ void __launch_bounds__(BLK, 4) k_loop(const float* __restrict__ Wout,
                                                 const float* __restrict__ bout,
                                                 float* __restrict__ out, int out_size){
    __shared__ double sE[Rr], sN[Rr];
    __shared__ float  su[Rr];
    __shared__ float  swt[Hh*Cc];
    __shared__ float  sbv[Cc];
    int tid  = threadIdx.x;
    int lane = tid & 31;
    int gwarp = blockIdx.x*WPB + (tid >> 5);

    for (int k = 0; k < 8; k++){
        int act = *(volatile int*)&g_act;
        if (act){
            if (tid < Rr){ sE[tid] = 0.0; sN[tid] = 0.0; }
            __syncthreads();
            for (int n = gwarp; n < Nn; n += NWARPS){
                float x0, x1, x2, x3;
                {   // own row: written by this same warp last combine -> L1-safe
                    uint2 rv = *(const uint2*)(g_xh + (size_t)n*Hh + lane*4);
                    float2 f0 = __half22float2(*(const __half2*)&rv.x);
                    float2 f1 = __half22float2(*(const __half2*)&rv.y);
                    x0 = f0.x; x1 = f0.y; x2 = f1.x; x3 = f1.y;
                }
                float sq = wsum(x0*x0 + x1*x1 + x2*x2 + x3*x3);
                int e = g_rowptr[n];
                #pragma unroll
                for (int r = 0; r < Rr; r++){
                    int len = g_degi[r*Nn + n];
                    if (len > 0){
                        float m0=0.f, m1=0.f, m2=0.f, m3=0.f, dt=0.f;
                        int e1 = e + len;
                        for (; e + 4 <= e1; e += 4){
                            int2 c0p = g_csr[e],   c1p = g_csr[e+1];
                            int2 c2p = g_csr[e+2], c3p = g_csr[e+3];
                            float a0,a1,a2,a3, b0,b1,b2,b3, c0,c1,c2,c3, q0,q1,q2,q3;
                            ld_row_cg(g_xh, c0p.x, lane, a0,a1,a2,a3);
                            ld_row_cg(g_xh, c1p.x, lane, b0,b1,b2,b3);
                            ld_row_cg(g_xh, c2p.x, lane, c0,c1,c2,c3);
                            ld_row_cg(g_xh, c3p.x, lane, q0,q1,q2,q3);
                            m0 += a0+b0+c0+q0; m1 += a1+b1+c1+q1;
                            m2 += a2+b2+c2+q2; m3 += a3+b3+c3+q3;
                            dt += __int_as_float(c0p.y)*(x0*a0 + x1*a1 + x2*a2 + x3*a3);
                            dt += __int_as_float(c1p.y)*(x0*b0 + x1*b1 + x2*b2 + x3*b3);
                            dt += __int_as_float(c2p.y)*(x0*c0 + x1*c1 + x2*c2 + x3*c3);
                            dt += __int_as_float(c3p.y)*(x0*q0 + x1*q1 + x2*q2 + x3*q3);
                        }
                        for (; e < e1; e++){
                            int2 cp = g_csr[e];
                            float a0,a1,a2,a3;
                            ld_row_cg(g_xh, cp.x, lane, a0,a1,a2,a3);
                            m0 += a0; m1 += a1; m2 += a2; m3 += a3;
                            dt += __int_as_float(cp.y)*(x0*a0 + x1*a1 + x2*a2 + x3*a3);
                        }
                        float inv = 1.f/(float)len;
                        __half2 p0 = __floats2half2_rn(m0*inv, m1*inv);
                        __half2 p1 = __floats2half2_rn(m2*inv, m3*inv);
                        uint2 pw; pw.x = *(unsigned*)&p0; pw.y = *(unsigned*)&p1;
                        *(uint2*)(g_msgh + ((size_t)r*Nn + n)*Hh + lane*4) = pw;
                        dt = wsum(dt);
                        if (lane == 0){
                            atomicAdd(&sE[r], (double)dt);
                            atomicAdd(&sN[r], (double)sq);
                        }
                    }
                }
            }
            __syncthreads();
            if (tid < Rr){
                if (sE[tid] != 0.0) atomicAdd(&g_edge[tid], sE[tid]);
                if (sN[tid] != 0.0) atomicAdd(&g_node[tid], sN[tid]);
            }
        }
        gbar(act, k);                       // last-arriving block runs mirror descent

        int still = *(volatile int*)&g_still;
        if (still){
            if (tid < Rr) su[tid] = *(volatile float*)&g_u[tid];
            __syncthreads();
            const float c1 = 1.f/21.f, c2 = 20.f/21.f;
            for (int n = gwarp; n < Nn; n += NWARPS){
                float4 xv = *(const float4*)(g_xa + (size_t)n*Hh + lane*4);
                float a0=0.f, a1=0.f, a2=0.f, a3=0.f;
                #pragma unroll
                for (int r = 0; r < Rr; r++){
                    if (g_degi[r*Nn + n] > 0){
                        uint2 rv = *(const uint2*)(g_msgh + ((size_t)r*Nn + n)*Hh + lane*4);
                        float2 f0 = __half22float2(*(const __half2*)&rv.x);
                        float2 f1 = __half22float2(*(const __half2*)&rv.y);
                        float ur = su[r];
                        a0 += ur*f0.x; a1 += ur*f0.y; a2 += ur*f1.x; a3 += ur*f1.y;
                    }
                }
                float4 o = make_float4(xv.x*c1 + c2*a0, xv.y*c1 + c2*a1,
                                       xv.z*c1 + c2*a2, xv.w*c1 + c2*a3);
                *(float4*)(g_xa + (size_t)n*Hh + lane*4) = o;
                __half2 p0 = __floats2half2_rn(o.x, o.y);
                __half2 p1 = __floats2half2_rn(o.z, o.w);
                uint2 pw; pw.x = *(unsigned*)&p0; pw.y = *(unsigned*)&p1;
                *(uint2*)(g_xh + (size_t)n*Hh + lane*4) = pw;
            }
        }
        gbar(0, 0);
    }

    // ---------- final: logits + output packing ----------
    for (int i = tid; i < Hh*Cc; i += BLK) swt[i] = Wout[i];
    if (tid < Cc) sbv[tid] = bout[tid];
    __syncthreads();
    bool full = (out_size >= OFF_U + Rr);
    for (int n = gwarp; n < Nn; n += NWARPS){
        float4 xv = *(const float4*)(g_xa + (size_t)n*Hh + lane*4);
        if (full) *(float4*)(out + OFF_X + (size_t)n*Hh + lane*4) = xv;
        float xs[4] = {xv.x, xv.y, xv.z, xv.w};
        float acc[Cc];
        #pragma unroll
        for (int c = 0; c < Cc; c++) acc[c] = 0.f;
        #pragma unroll
        for (int i = 0; i < 4; i++){
            const float* wr = &swt[(lane*4 + i)*Cc];
            #pragma unroll
            for (int c = 0; c < Cc; c++) acc[c] += xs[i]*wr[c];
        }
        #pragma unroll
        for (int c = 0; c < Cc; c++) acc[c] = wsum(acc[c]);
        if (lane == 0){
            #pragma unroll
            for (int c = 0; c < Cc; c++) out[(size_t)n*Cc + c] = acc[c] + sbv[c];
        }
    }
    if (full && blockIdx.x == 0 && tid < Rr) out[OFF_U + tid] = *(volatile float*)&g_u[tid];
}

// ---------------- host launcher ----------------
extern "C" void kernel_launch(void* const* d_in, const int* in_sizes, int n_in,
                              void* d_out, int out_size){
    const float* feat0 = (const float*)d_in[0];
    const float* feat1 = (const float*)d_in[1];
    const float* W0   = (const float*)d_in[2];  const float* b0   = (const float*)d_in[3];
    const float* W1   = (const float*)d_in[4];  const float* b1   = (const float*)d_in[5];
    const float* Wm1  = (const float*)d_in[6];  const float* bm1  = (const float*)d_in[7];
    const float* Wm2  = (const float*)d_in[8];  const float* bm2  = (const float*)d_in[9];
    const float* Wout = (const float*)d_in[10]; const float* bout = (const float*)d_in[11];
    const int*   src  = (const int*)d_in[12];
    const int*   dst  = (const int*)d_in[13];
    const int*   rel  = (const int*)d_in[14];
    float* out = (float*)d_out;

    const int EB = (Ee + 255)/256;          // 2344
    const int NB_SCAN = (Nn + 1023)/1024;   // 30

    // fork-join resources created once, on the first (non-captured) call
    static cudaStream_t s2 = nullptr;
    static cudaEvent_t evFork = nullptr, evJoin = nullptr;
    if (s2 == nullptr){
        cudaStreamCreateWithFlags(&s2, cudaStreamNonBlocking);
        cudaEventCreateWithFlags(&evFork, cudaEventDisableTiming);
        cudaEventCreateWithFlags(&evJoin, cudaEventDisableTiming);
    }

    k_init<<<256, 256>>>();

    // fork: graph-prep chain on s2, MLP chain on the launch stream
    cudaEventRecord(evFork, 0);
    cudaStreamWaitEvent(s2, evFork, 0);

    k_count<<<EB, 256, 0, s2>>>(src, rel);
    k_scan1<<<NB_SCAN, 1024, 0, s2>>>();
    k_scan2<<<1, 32, 0, s2>>>(NB_SCAN);
    k_scan3c<<<(Nn+255)/256, 256, 0, s2>>>();
    k_scatter2<<<EB, 256, 0, s2>>>(src, dst, rel);
    cudaEventRecord(evJoin, s2);

    k_typed<<<NB0 + NB1, 256>>>(feat0, W0, b0, feat1, W1, b1);   // 470 blocks
    k_mlp2<<<(Nn+63)/64, 256>>>(Wm1, bm1, Wm2, bm2);             // 469 blocks

    // join
    cudaStreamWaitEvent(0, evJoin, 0);

    k_loop<<<GRID, BLK>>>(Wout, bout, out, out_size);
}

// round 14
// speedup vs baseline: 1.1957x; 1.1957x over previous
#include <cuda_runtime.h>
#include <cuda_fp16.h>
#include <math.h>

#define Nn 30000
#define NN0 18000
#define NN1 12000
#define Rr 5
#define Ee 600000
#define Hh 128
#define Cc 8
#define OFF_X (Nn*Cc)            /* 240000   */
#define OFF_U (OFF_X + Nn*Hh)    /* 4080000  */

#define GRID 592                  /* 148 SMs x 4 co-resident blocks */
#define BLK  256
#define WPB  (BLK/32)
#define NWARPS (GRID*WPB)

#define NB0 ((NN0+63)/64)         /* 282 */
#define NB1 ((NN1+63)/64)         /* 188 */

// ---------------- device scratch (static, no allocation) ----------------
__device__ float  g_h [Nn*Hh];
__device__ float  g_xa[Nn*Hh];                 // fp32 x, updated in place
__device__ __half g_xh[Nn*Hh];                 // fp16 mirror of current x
__device__ __half g_msgh[(size_t)Rr*Nn*Hh];    // per-relation messages fp16
__device__ int    g_degi[Rr*Nn];
__device__ int    g_cnt[Nn];
__device__ int    g_rowptr[Nn+1];
__device__ int    g_cur2[Rr*Nn];
__device__ int    g_bsums[64];
__device__ int2   g_csr[Ee];                   // (dst, edinv-as-int) packed
__device__ double g_node[Rr];
__device__ double g_edge[Rr];
__device__ float  g_u[Rr];
__device__ float  g_clt;
__device__ int    g_act;
__device__ int    g_still;
__device__ unsigned g_bcount;
__device__ volatile unsigned g_bsense;

__device__ __forceinline__ float wsum(float v){
    #pragma unroll
    for (int o = 16; o; o >>= 1) v += __shfl_xor_sync(0xffffffffu, v, o);
    return v;
}
__device__ __forceinline__ float n2n(float v){
    if (isnan(v)) return 0.f;
    if (isinf(v)) return v > 0.f ? 3.4028234663852886e38f : -3.4028234663852886e38f;
    return v;
}

// ---------------- init / graph preprocessing ----------------
__global__ void k_init(){
    int i = blockIdx.x*blockDim.x + threadIdx.x;
    int st = gridDim.x*blockDim.x;
    for (int j = i; j < Rr*Nn; j += st) g_degi[j] = 0;
    for (int j = i; j < Nn;    j += st) g_cnt[j]  = 0;
    if (i < Rr) { g_node[i] = 0.0; g_edge[i] = 0.0; g_u[i] = 0.2f; }
    if (i == 0) { g_act = 1; g_still = 1; g_bcount = 0u; g_bsense = 0u; }
}

__global__ void k_count(const int* __restrict__ src, const int* __restrict__ rel){
    int i = blockIdx.x*blockDim.x + threadIdx.x;
    if (i < Ee) {
        atomicAdd(&g_degi[rel[i]*Nn + src[i]], 1);
        atomicAdd(&g_cnt[src[i]], 1);
    }
}

__global__ void k_scan1(){
    __shared__ int s[1024];
    int i = blockIdx.x*1024 + threadIdx.x;
    int v = (i < Nn) ? g_cnt[i] : 0;
    s[threadIdx.x] = v;
    __syncthreads();
    for (int off = 1; off < 1024; off <<= 1){
        int t = 0;
        if (threadIdx.x >= off) t = s[threadIdx.x - off];
        __syncthreads();
        if (threadIdx.x >= off) s[threadIdx.x] += t;
        __syncthreads();
    }
    if (i < Nn) g_rowptr[i] = s[threadIdx.x] - v;
    if (threadIdx.x == 1023) g_bsums[blockIdx.x] = s[1023];
}

__global__ void k_scan2(int nb){
    if (threadIdx.x == 0){
        int run = 0;
        for (int b = 0; b < nb; b++){ int t = g_bsums[b]; g_bsums[b] = run; run += t; }
    }
}

// fused: finalize rowptr + per-(node,rel) cursors
__global__ void k_scan3c(){
    int i = blockIdx.x*blockDim.x + threadIdx.x;
    if (i < Nn){
        int base = g_rowptr[i] + g_bsums[i >> 10];
        g_rowptr[i] = base;
        #pragma unroll
        for (int r = 0; r < Rr; r++){
            g_cur2[r*Nn + i] = base;
            base += g_degi[r*Nn + i];
        }
    }
    if (i == 0) g_rowptr[Nn] = Ee;
}

__global__ void k_scatter2(const int* __restrict__ src, const int* __restrict__ dst,
                           const int* __restrict__ rel){
    int i = blockIdx.x*blockDim.x + threadIdx.x;
    if (i >= Ee) return;
    int s = src[i], r = rel[i], d = dst[i];
    int pos = atomicAdd(&g_cur2[r*Nn + s], 1);
    int degs = g_degi[r*Nn + s];
    int degd = g_degi[r*Nn + d];
    float ei = (1.f/sqrtf((float)degs)) * (degd > 0 ? 1.f/sqrtf((float)degd) : 0.f);
    int2 pk; pk.x = d; pk.y = __float_as_int(ei);
    g_csr[pos] = pk;
}

// ------- merged typed GEMM: blocks [0,NB0) do feat0@W0, [NB0,NB0+NB1) do feat1@W1 -------
__global__ void __launch_bounds__(256, 3) k_typed(const float* __restrict__ feat0,
                                                  const float* __restrict__ W0,
                                                  const float* __restrict__ b0,
                                                  const float* __restrict__ feat1,
                                                  const float* __restrict__ W1,
                                                  const float* __restrict__ b1){
    __shared__ float As[64*17];
    __shared__ float Bs[16*128];
    const float *A, *W, *bias;
    int lda, nrows, rowbase, K, blk;
    if (blockIdx.x < NB0){
        A = feat0; W = W0; bias = b0; lda = 256; nrows = NN0; rowbase = 0;   K = 256; blk = blockIdx.x;
    } else {
        A = feat1; W = W1; bias = b1; lda = 128; nrows = NN1; rowbase = NN0; K = 128; blk = blockIdx.x - NB0;
    }
    int tid  = threadIdx.x;
    int tcol = tid & 31, trow = tid >> 5;
    int row0 = blk * 64;
    float acc[8][4];
    #pragma unroll
    for (int i = 0; i < 8; i++){ acc[i][0]=0.f; acc[i][1]=0.f; acc[i][2]=0.f; acc[i][3]=0.f; }

    for (int k0 = 0; k0 < K; k0 += 16){
        #pragma unroll
        for (int i = 0; i < 4; i++){
            int lin = tid + 256*i;
            int r = lin >> 4, k = lin & 15;
            int gr = row0 + r;
            As[r*17+k] = (gr < nrows) ? A[(size_t)gr*lda + k0 + k] : 0.f;
        }
        #pragma unroll
        for (int i = 0; i < 8; i++){
            int lin = tid + 256*i;
            int k = lin >> 7, c = lin & 127;
            Bs[k*128+c] = W[(size_t)(k0+k)*128 + c];
        }
        __syncthreads();
        #pragma unroll
        for (int k = 0; k < 16; k++){
            float4 bv = *(const float4*)&Bs[k*128 + tcol*4];
            #pragma unroll
            for (int ri = 0; ri < 8; ri++){
                float a = As[(trow*8+ri)*17 + k];
                acc[ri][0] += a*bv.x; acc[ri][1] += a*bv.y;
                acc[ri][2] += a*bv.z; acc[ri][3] += a*bv.w;
            }
        }
        __syncthreads();
    }
    float4 bv = *(const float4*)&bias[tcol*4];
    #pragma unroll
    for (int ri = 0; ri < 8; ri++){
        int gr = row0 + trow*8 + ri;
        if (gr < nrows){
            float4 o = make_float4(acc[ri][0]+bv.x, acc[ri][1]+bv.y,
                                   acc[ri][2]+bv.z, acc[ri][3]+bv.w);
            *(float4*)&g_h[(size_t)(rowbase+gr)*Hh + tcol*4] = o;
        }
    }
}

// ---------------- stage B: LN(h@Wm1+b)->relu -> @Wm2+b -> standardize ----------------
__global__ void __launch_bounds__(256, 3) k_mlp2(const float* __restrict__ Wm1, const float* __restrict__ bm1,
                                                 const float* __restrict__ Wm2, const float* __restrict__ bm2){
    __shared__ float As[64*17];
    __shared__ float Bs[16*128];
    __shared__ float Zs[64*132];
    int tid  = threadIdx.x;
    int tcol = tid & 31, trow = tid >> 5;
    int row0 = blockIdx.x * 64;
    float acc[8][4];
    #pragma unroll
    for (int i = 0; i < 8; i++){ acc[i][0]=0.f; acc[i][1]=0.f; acc[i][2]=0.f; acc[i][3]=0.f; }

    for (int k0 = 0; k0 < 128; k0 += 16){
        #pragma unroll
        for (int i = 0; i < 4; i++){
            int lin = tid + 256*i;
            int r = lin >> 4, k = lin & 15;
            int gr = row0 + r;
            As[r*17+k] = (gr < Nn) ? g_h[(size_t)gr*Hh + k0 + k] : 0.f;
        }
        #pragma unroll
        for (int i = 0; i < 8; i++){
            int lin = tid + 256*i;
            int k = lin >> 7, c = lin & 127;
            Bs[k*128+c] = Wm1[(size_t)(k0+k)*128 + c];
        }
        __syncthreads();
        #pragma unroll
        for (int k = 0; k < 16; k++){
            float4 bv = *(const float4*)&Bs[k*128 + tcol*4];
            #pragma unroll
            for (int ri = 0; ri < 8; ri++){
                float a = As[(trow*8+ri)*17 + k];
                acc[ri][0] += a*bv.x; acc[ri][1] += a*bv.y;
                acc[ri][2] += a*bv.z; acc[ri][3] += a*bv.w;
            }
        }
        __syncthreads();
    }
    float4 b1v = *(const float4*)&bm1[tcol*4];
    #pragma unroll
    for (int ri = 0; ri < 8; ri++){
        float v0 = acc[ri][0]+b1v.x, v1 = acc[ri][1]+b1v.y;
        float v2 = acc[ri][2]+b1v.z, v3 = acc[ri][3]+b1v.w;
        float s1 = wsum(v0+v1+v2+v3);
        float s2 = wsum(v0*v0+v1*v1+v2*v2+v3*v3);
        float m  = s1 * (1.f/128.f);
        float var = s2 * (1.f/128.f) - m*m;
        float rs = rsqrtf(var + 1e-5f);
        int r = trow*8 + ri;
        float4 z = make_float4(fmaxf(0.f,(v0-m)*rs), fmaxf(0.f,(v1-m)*rs),
                               fmaxf(0.f,(v2-m)*rs), fmaxf(0.f,(v3-m)*rs));
        *(float4*)&Zs[r*132 + tcol*4] = z;
    }
    __syncthreads();

    float acc2[8][4];
    #pragma unroll
    for (int i = 0; i < 8; i++){ acc2[i][0]=0.f; acc2[i][1]=0.f; acc2[i][2]=0.f; acc2[i][3]=0.f; }
    for (int k0 = 0; k0 < 128; k0 += 16){
        #pragma unroll
        for (int i = 0; i < 8; i++){
            int lin = tid + 256*i;
            int k = lin >> 7, c = lin & 127;
            Bs[k*128+c] = Wm2[(size_t)(k0+k)*128 + c];
        }
        __syncthreads();
        #pragma unroll
        for (int k = 0; k < 16; k++){
            float4 bv = *(const float4*)&Bs[k*128 + tcol*4];
            #pragma unroll
            for (int ri = 0; ri < 8; ri++){
                float a = Zs[(trow*8+ri)*132 + k0 + k];
                acc2[ri][0] += a*bv.x; acc2[ri][1] += a*bv.y;
                acc2[ri][2] += a*bv.z; acc2[ri][3] += a*bv.w;
            }
        }
        __syncthreads();
    }
    float4 b2v = *(const float4*)&bm2[tcol*4];
    #pragma unroll
    for (int ri = 0; ri < 8; ri++){
        int gr = row0 + trow*8 + ri;
        float v0 = acc2[ri][0]+b2v.x, v1 = acc2[ri][1]+b2v.y;
        float v2 = acc2[ri][2]+b2v.z, v3 = acc2[ri][3]+b2v.w;
        float s1 = wsum(v0+v1+v2+v3);
        float s2 = wsum(v0*v0+v1*v1+v2*v2+v3*v3);
        float m  = s1 * (1.f/128.f);
        float varu = (s2 - 128.f*m*m) * (1.f/127.f);
        float sd = sqrtf(varu);
        float o0 = n2n((v0-m)/sd), o1 = n2n((v1-m)/sd);
        float o2 = n2n((v2-m)/sd), o3 = n2n((v3-m)/sd);
        if (gr < Nn){
            *(float4*)&g_xa[(size_t)gr*Hh + tcol*4] = make_float4(o0,o1,o2,o3);
            __half2 p0 = __floats2half2_rn(o0, o1);
            __half2 p1 = __floats2half2_rn(o2, o3);
            uint2 pw;
            pw.x = *(unsigned*)&p0; pw.y = *(unsigned*)&p1;
            *(uint2*)&g_xh[(size_t)gr*Hh + tcol*4] = pw;
        }
    }
}

// ---------------- mirror descent (inside grid barrier; fast-math exp) ----------------
__device__ void dev_md(int kiter){
    float w[Rr]; float l1 = 0.f;
    #pragma unroll
    for (int r = 0; r < Rr; r++){
        double nv = *(volatile double*)&g_node[r];
        double ev = *(volatile double*)&g_edge[r];
        w[r] = (float)((nv - ev) / (double)Nn);
        l1 += fabsf(w[r]);
        *(volatile double*)&g_node[r] = 0.0;
        *(volatile double*)&g_edge[r] = 0.0;
    }
    float clt;
    if (kiter == 0){ clt = l1; *(volatile float*)&g_clt = l1; }
    else clt = *(volatile float*)&g_clt;
    float u[Rr];
    #pragma unroll
    for (int r = 0; r < Rr; r++) u[r] = *(volatile float*)&g_u[r];
    float fi = l1 + 3.0f;          // ratio = 2*L2/L1 = 3
    const float tln = 2.f*1.6094379124341003f;   // 2*log(5)
    float inv_fi2 = 1.f/(fi*fi);
    bool ia = true;
    for (int t = 1; t <= 20 && ia; t++){
        float Tt = sqrtf(tln * inv_fi2 / (float)t);
        float uta[Rr]; float s = 0.f;
        #pragma unroll
        for (int r = 0; r < Rr; r++){ uta[r] = u[r]*__expf(-Tt*(3.f*u[r] + w[r])); s += uta[r]; }
        float is = 1.f/s;
        float dif = 0.f;
        #pragma unroll
        for (int r = 0; r < Rr; r++){
            uta[r] *= is;
            float d = u[r] - uta[r];
            dif += d*d;
            u[r] = uta[r];
        }
        ia = (dif >= 1e-6f);
    }
    #pragma unroll
    for (int r = 0; r < Rr; r++) *(volatile float*)&g_u[r] = u[r];
    int still = (l1 / clt >= 0.3f) ? 1 : 0;
    *(volatile int*)&g_still = still;
    *(volatile int*)&g_act   = still;
}

// ---------------- grid barrier (sense-reversing); last block may run md ----------------
__device__ __forceinline__ void gbar(int run_md, int kiter){
    __syncthreads();
    if (threadIdx.x == 0){
        unsigned s = g_bsense;
        __threadfence();
        unsigned a = atomicAdd(&g_bcount, 1u);
        if (a == (unsigned)(GRID - 1)){
            if (run_md) dev_md(kiter);
            g_bcount = 0u;
            __threadfence();
            g_bsense = s ^ 1u;
        } else {
            while (g_bsense == s) __nanosleep(64);
            __threadfence();
        }
    }
    __syncthreads();
}

// helper: fp16 row fetch (L2-only, cross-SM coherent) -> 4 floats
__device__ __forceinline__ void ld_row_cg(const __half* __restrict__ xh, int node, int lane,
                                          float& a, float& b, float& c, float& d){
    unsigned long long rv = __ldcg((const unsigned long long*)(xh + (size_t)node*Hh + lane*4));
    unsigned lo = (unsigned)rv, hi = (unsigned)(rv >> 32);
    float2 f0 = __half22float2(*(__half2*)&lo);
    float2 f1 = __half22float2(*(__half2*)&hi);
    a = f0.x; b = f0.y; c = f1.x; d = f1.y;
}

// ---------------- persistent loop: 8 x (gather -> md -> combine) + final output ----------------
__global__ void __launch_bounds__(BLK, 4) k_loop(const float* __restrict__ Wout,
                                                 const float* __restrict__ bout,
                                                 float* __restrict__ out, int out_size){
    __shared__ double sE[Rr], sN[Rr];
    __shared__ float  su[Rr];
    __shared__ float  swt[Hh*Cc];
    __shared__ float  sbv[Cc];
    int tid  = threadIdx.x;
    int lane = tid & 31;
    int gwarp = blockIdx.x*WPB + (tid >> 5);

    for (int k = 0; k < 8; k++){
        int act = *(volatile int*)&g_act;
        if (act){
            if (tid < Rr){ sE[tid] = 0.0; sN[tid] = 0.0; }
            __syncthreads();
            for (int n = gwarp; n < Nn; n += NWARPS){
                float x0, x1, x2, x3;
                {   // own row: written by this same warp last combine -> L1-safe
                    uint2 rv = *(const uint2*)(g_xh + (size_t)n*Hh + lane*4);
                    float2 f0 = __half22float2(*(const __half2*)&rv.x);
                    float2 f1 = __half22float2(*(const __half2*)&rv.y);
                    x0 = f0.x; x1 = f0.y; x2 = f1.x; x3 = f1.y;
                }
                float sq = wsum(x0*x0 + x1*x1 + x2*x2 + x3*x3);
                int e = g_rowptr[n];
                #pragma unroll
                for (int r = 0; r < Rr; r++){
                    int len = g_degi[r*Nn + n];
                    if (len > 0){
                        float m0=0.f, m1=0.f, m2=0.f, m3=0.f, dt=0.f;
                        int e1 = e + len;
                        for (; e + 4 <= e1; e += 4){
                            int2 c0p = g_csr[e],   c1p = g_csr[e+1];
                            int2 c2p = g_csr[e+2], c3p = g_csr[e+3];
                            float a0,a1,a2,a3, b0,b1,b2,b3, c0,c1,c2,c3, q0,q1,q2,q3;
                            ld_row_cg(g_xh, c0p.x, lane, a0,a1,a2,a3);
                            ld_row_cg(g_xh, c1p.x, lane, b0,b1,b2,b3);
                            ld_row_cg(g_xh, c2p.x, lane, c0,c1,c2,c3);
                            ld_row_cg(g_xh, c3p.x, lane, q0,q1,q2,q3);
                            m0 += a0+b0+c0+q0; m1 += a1+b1+c1+q1;
                            m2 += a2+b2+c2+q2; m3 += a3+b3+c3+q3;
                            dt += __int_as_float(c0p.y)*(x0*a0 + x1*a1 + x2*a2 + x3*a3);
                            dt += __int_as_float(c1p.y)*(x0*b0 + x1*b1 + x2*b2 + x3*b3);
                            dt += __int_as_float(c2p.y)*(x0*c0 + x1*c1 + x2*c2 + x3*c3);
                            dt += __int_as_float(c3p.y)*(x0*q0 + x1*q1 + x2*q2 + x3*q3);
                        }
                        for (; e < e1; e++){
                            int2 cp = g_csr[e];
                            float a0,a1,a2,a3;
                            ld_row_cg(g_xh, cp.x, lane, a0,a1,a2,a3);
                            m0 += a0; m1 += a1; m2 += a2; m3 += a3;
                            dt += __int_as_float(cp.y)*(x0*a0 + x1*a1 + x2*a2 + x3*a3);
                        }
                        float inv = 1.f/(float)len;
                        __half2 p0 = __floats2half2_rn(m0*inv, m1*inv);
                        __half2 p1 = __floats2half2_rn(m2*inv, m3*inv);
                        uint2 pw; pw.x = *(unsigned*)&p0; pw.y = *(unsigned*)&p1;
                        *(uint2*)(g_msgh + ((size_t)r*Nn + n)*Hh + lane*4) = pw;
                        dt = wsum(dt);
                        if (lane == 0){
                            atomicAdd(&sE[r], (double)dt);
                            atomicAdd(&sN[r], (double)sq);
                        }
                    }
                }
            }
            __syncthreads();
            if (tid < Rr){
                if (sE[tid] != 0.0) atomicAdd(&g_edge[tid], sE[tid]);
                if (sN[tid] != 0.0) atomicAdd(&g_node[tid], sN[tid]);
            }
        }
        gbar(act, k);                       // last-arriving block runs mirror descent

        int still = *(volatile int*)&g_still;
        if (still){
            if (tid < Rr) su[tid] = *(volatile float*)&g_u[tid];
            __syncthreads();
            const float c1 = 1.f/21.f, c2 = 20.f/21.f;
            for (int n = gwarp; n < Nn; n += NWARPS){
                float4 xv = *(const float4*)(g_xa + (size_t)n*Hh + lane*4);
                float a0=0.f, a1=0.f, a2=0.f, a3=0.f;
                #pragma unroll
                for (int r = 0; r < Rr; r++){
                    if (g_degi[r*Nn + n] > 0){
                        uint2 rv = *(const uint2*)(g_msgh + ((size_t)r*Nn + n)*Hh + lane*4);
                        float2 f0 = __half22float2(*(const __half2*)&rv.x);
                        float2 f1 = __half22float2(*(const __half2*)&rv.y);
                        float ur = su[r];
                        a0 += ur*f0.x; a1 += ur*f0.y; a2 += ur*f1.x; a3 += ur*f1.y;
                    }
                }
                float4 o = make_float4(xv.x*c1 + c2*a0, xv.y*c1 + c2*a1,
                                       xv.z*c1 + c2*a2, xv.w*c1 + c2*a3);
                *(float4*)(g_xa + (size_t)n*Hh + lane*4) = o;
                __half2 p0 = __floats2half2_rn(o.x, o.y);
                __half2 p1 = __floats2half2_rn(o.z, o.w);
                uint2 pw; pw.x = *(unsigned*)&p0; pw.y = *(unsigned*)&p1;
                *(uint2*)(g_xh + (size_t)n*Hh + lane*4) = pw;
            }
        }
        gbar(0, 0);
    }

    // ---------- final: logits + output packing ----------
    for (int i = tid; i < Hh*Cc; i += BLK) swt[i] = Wout[i];
    if (tid < Cc) sbv[tid] = bout[tid];
    __syncthreads();
    bool full = (out_size >= OFF_U + Rr);
    for (int n = gwarp; n < Nn; n += NWARPS){
        float4 xv = *(const float4*)(g_xa + (size_t)n*Hh + lane*4);
        if (full) *(float4*)(out + OFF_X + (size_t)n*Hh + lane*4) = xv;
        float xs[4] = {xv.x, xv.y, xv.z, xv.w};
        float acc[Cc];
        #pragma unroll
        for (int c = 0; c < Cc; c++) acc[c] = 0.f;
        #pragma unroll
        for (int i = 0; i < 4; i++){
            const float* wr = &swt[(lane*4 + i)*Cc];
            #pragma unroll
            for (int c = 0; c < Cc; c++) acc[c] += xs[i]*wr[c];
        }
        #pragma unroll
        for (int c = 0; c < Cc; c++) acc[c] = wsum(acc[c]);
        if (lane == 0){
            #pragma unroll
            for (int c = 0; c < Cc; c++) out[(size_t)n*Cc + c] = acc[c] + sbv[c];
        }
    }
    if (full && blockIdx.x == 0 && tid < Rr) out[OFF_U + tid] = *(volatile float*)&g_u[tid];
}

// ---------------- host launcher ----------------
extern "C" void kernel_launch(void* const* d_in, const int* in_sizes, int n_in,
                              void* d_out, int out_size){
    const float* feat0 = (const float*)d_in[0];
    const float* feat1 = (const float*)d_in[1];
    const float* W0   = (const float*)d_in[2];  const float* b0   = (const float*)d_in[3];
    const float* W1   = (const float*)d_in[4];  const float* b1   = (const float*)d_in[5];
    const float* Wm1  = (const float*)d_in[6];  const float* bm1  = (const float*)d_in[7];
    const float* Wm2  = (const float*)d_in[8];  const float* bm2  = (const float*)d_in[9];
    const float* Wout = (const float*)d_in[10]; const float* bout = (const float*)d_in[11];
    const int*   src  = (const int*)d_in[12];
    const int*   dst  = (const int*)d_in[13];
    const int*   rel  = (const int*)d_in[14];
    float* out = (float*)d_out;

    const int EB = (Ee + 255)/256;          // 2344
    const int NB_SCAN = (Nn + 1023)/1024;   // 30

    // fork-join resources created once, on the first (non-captured) call
    static cudaStream_t s2 = nullptr;
    static cudaEvent_t evFork = nullptr, evJoin = nullptr;
    if (s2 == nullptr){
        cudaStreamCreateWithFlags(&s2, cudaStreamNonBlocking);
        cudaEventCreateWithFlags(&evFork, cudaEventDisableTiming);
        cudaEventCreateWithFlags(&evJoin, cudaEventDisableTiming);
    }

    k_init<<<256, 256>>>();

    // fork: graph-prep chain on s2, MLP chain on the launch stream
    cudaEventRecord(evFork, 0);
    cudaStreamWaitEvent(s2, evFork, 0);

    k_count<<<EB, 256, 0, s2>>>(src, rel);
    k_scan1<<<NB_SCAN, 1024, 0, s2>>>();
    k_scan2<<<1, 32, 0, s2>>>(NB_SCAN);
    k_scan3c<<<(Nn+255)/256, 256, 0, s2>>>();
    k_scatter2<<<EB, 256, 0, s2>>>(src, dst, rel);
    cudaEventRecord(evJoin, s2);

    k_typed<<<NB0 + NB1, 256>>>(feat0, W0, b0, feat1, W1, b1);   // 470 blocks
    k_mlp2<<<(Nn+63)/64, 256>>>(Wm1, bm1, Wm2, bm2);             // 469 blocks

    // join
    cudaStreamWaitEvent(0, evJoin, 0);

    k_loop<<<GRID, BLK>>>(Wout, bout, out, out_size);
}

// round 15
// speedup vs baseline: 1.2722x; 1.0640x over previous
#include <cuda_runtime.h>
#include <cuda_fp16.h>
#include <math.h>

#define Nn 30000
#define NN0 18000
#define NN1 12000
#define Rr 5
#define Ee 600000
#define Hh 128
#define Cc 8
#define OFF_X (Nn*Cc)            /* 240000   */
#define OFF_U (OFF_X + Nn*Hh)    /* 4080000  */

#define GRID 592                  /* 148 SMs x 4 co-resident blocks */
#define BLK  256
#define WPB  (BLK/32)
#define NWARPS (GRID*WPB)

#define NB0 ((NN0+63)/64)         /* 282 */
#define NB1 ((NN1+63)/64)         /* 188 */

// ---------------- device scratch (static, no allocation) ----------------
__device__ float  g_h [Nn*Hh];
__device__ float  g_xa[Nn*Hh];                 // fp32 x, updated in place
__device__ __half g_xh[Nn*Hh];                 // fp16 mirror of current x
__device__ __half g_msgh[(size_t)Rr*Nn*Hh];    // per-relation messages fp16
__device__ int    g_degi[Rr*Nn];
__device__ int    g_cnt[Nn];
__device__ int    g_rowptr[Nn+1];
__device__ int    g_cur2[Rr*Nn];
__device__ int    g_bsums[64];
__device__ int2   g_csr[Ee];                   // (dst, edinv-as-int) packed
__device__ double g_node[Rr];
__device__ double g_edge[Rr];
__device__ float  g_u[Rr];
__device__ float  g_clt;
__device__ int    g_act;
__device__ int    g_still;
__device__ unsigned g_bcount;
__device__ volatile unsigned g_bsense;

__device__ __forceinline__ float wsum(float v){
    #pragma unroll
    for (int o = 16; o; o >>= 1) v += __shfl_xor_sync(0xffffffffu, v, o);
    return v;
}
__device__ __forceinline__ float n2n(float v){
    if (isnan(v)) return 0.f;
    if (isinf(v)) return v > 0.f ? 3.4028234663852886e38f : -3.4028234663852886e38f;
    return v;
}

// ---------------- init / graph preprocessing ----------------
__global__ void k_init(){
    int i = blockIdx.x*blockDim.x + threadIdx.x;
    int st = gridDim.x*blockDim.x;
    for (int j = i; j < Rr*Nn; j += st) g_degi[j] = 0;
    for (int j = i; j < Nn;    j += st) g_cnt[j]  = 0;
    if (i < Rr) { g_node[i] = 0.0; g_edge[i] = 0.0; g_u[i] = 0.2f; }
    if (i == 0) { g_act = 1; g_still = 1; g_bcount = 0u; g_bsense = 0u; }
}

__global__ void k_count(const int* __restrict__ src, const int* __restrict__ rel){
    int i = blockIdx.x*blockDim.x + threadIdx.x;
    if (i < Ee) {
        atomicAdd(&g_degi[rel[i]*Nn + src[i]], 1);
        atomicAdd(&g_cnt[src[i]], 1);
    }
}

__global__ void k_scan1(){
    __shared__ int s[1024];
    int i = blockIdx.x*1024 + threadIdx.x;
    int v = (i < Nn) ? g_cnt[i] : 0;
    s[threadIdx.x] = v;
    __syncthreads();
    for (int off = 1; off < 1024; off <<= 1){
        int t = 0;
        if (threadIdx.x >= off) t = s[threadIdx.x - off];
        __syncthreads();
        if (threadIdx.x >= off) s[threadIdx.x] += t;
        __syncthreads();
    }
    if (i < Nn) g_rowptr[i] = s[threadIdx.x] - v;
    if (threadIdx.x == 1023) g_bsums[blockIdx.x] = s[1023];
}

__global__ void k_scan2(int nb){
    if (threadIdx.x == 0){
        int run = 0;
        for (int b = 0; b < nb; b++){ int t = g_bsums[b]; g_bsums[b] = run; run += t; }
    }
}

// fused: finalize rowptr + per-(node,rel) cursors
__global__ void k_scan3c(){
    int i = blockIdx.x*blockDim.x + threadIdx.x;
    if (i < Nn){
        int base = g_rowptr[i] + g_bsums[i >> 10];
        g_rowptr[i] = base;
        #pragma unroll
        for (int r = 0; r < Rr; r++){
            g_cur2[r*Nn + i] = base;
            base += g_degi[r*Nn + i];
        }
    }
    if (i == 0) g_rowptr[Nn] = Ee;
}

__global__ void k_scatter2(const int* __restrict__ src, const int* __restrict__ dst,
                           const int* __restrict__ rel){
    int i = blockIdx.x*blockDim.x + threadIdx.x;
    if (i >= Ee) return;
    int s = src[i], r = rel[i], d = dst[i];
    int pos = atomicAdd(&g_cur2[r*Nn + s], 1);
    int degs = g_degi[r*Nn + s];
    int degd = g_degi[r*Nn + d];
    float ei = (1.f/sqrtf((float)degs)) * (degd > 0 ? 1.f/sqrtf((float)degd) : 0.f);
    int2 pk; pk.x = d; pk.y = __float_as_int(ei);
    g_csr[pos] = pk;
}

// ------- merged typed GEMM: blocks [0,NB0) do feat0@W0, [NB0,NB0+NB1) do feat1@W1 -------
__global__ void __launch_bounds__(256, 2) k_typed(const float* __restrict__ feat0,
                                                  const float* __restrict__ W0,
                                                  const float* __restrict__ b0,
                                                  const float* __restrict__ feat1,
                                                  const float* __restrict__ W1,
                                                  const float* __restrict__ b1){
    __shared__ float As[64*17];
    __shared__ float Bs[16*128];
    const float *A, *W, *bias;
    int lda, nrows, rowbase, K, blk;
    if (blockIdx.x < NB0){
        A = feat0; W = W0; bias = b0; lda = 256; nrows = NN0; rowbase = 0;   K = 256; blk = blockIdx.x;
    } else {
        A = feat1; W = W1; bias = b1; lda = 128; nrows = NN1; rowbase = NN0; K = 128; blk = blockIdx.x - NB0;
    }
    int tid  = threadIdx.x;
    int tcol = tid & 31, trow = tid >> 5;
    int row0 = blk * 64;
    float acc[8][4];
    #pragma unroll
    for (int i = 0; i < 8; i++){ acc[i][0]=0.f; acc[i][1]=0.f; acc[i][2]=0.f; acc[i][3]=0.f; }

    for (int k0 = 0; k0 < K; k0 += 16){
        #pragma unroll
        for (int i = 0; i < 4; i++){
            int lin = tid + 256*i;
            int r = lin >> 4, k = lin & 15;
            int gr = row0 + r;
            As[r*17+k] = (gr < nrows) ? A[(size_t)gr*lda + k0 + k] : 0.f;
        }
        #pragma unroll
        for (int i = 0; i < 8; i++){
            int lin = tid + 256*i;
            int k = lin >> 7, c = lin & 127;
            Bs[k*128+c] = W[(size_t)(k0+k)*128 + c];
        }
        __syncthreads();
        #pragma unroll
        for (int k = 0; k < 16; k++){
            float4 bv = *(const float4*)&Bs[k*128 + tcol*4];
            #pragma unroll
            for (int ri = 0; ri < 8; ri++){
                float a = As[(trow*8+ri)*17 + k];
                acc[ri][0] += a*bv.x; acc[ri][1] += a*bv.y;
                acc[ri][2] += a*bv.z; acc[ri][3] += a*bv.w;
            }
        }
        __syncthreads();
    }
    float4 bv = *(const float4*)&bias[tcol*4];
    #pragma unroll
    for (int ri = 0; ri < 8; ri++){
        int gr = row0 + trow*8 + ri;
        if (gr < nrows){
            float4 o = make_float4(acc[ri][0]+bv.x, acc[ri][1]+bv.y,
                                   acc[ri][2]+bv.z, acc[ri][3]+bv.w);
            *(float4*)&g_h[(size_t)(rowbase+gr)*Hh + tcol*4] = o;
        }
    }
}

// ---------------- stage B: LN(h@Wm1+b)->relu -> @Wm2+b -> standardize ----------------
__global__ void __launch_bounds__(256, 2) k_mlp2(const float* __restrict__ Wm1, const float* __restrict__ bm1,
                                                 const float* __restrict__ Wm2, const float* __restrict__ bm2){
    __shared__ float As[64*17];
    __shared__ float Bs[16*128];
    __shared__ float Zs[64*132];
    int tid  = threadIdx.x;
    int tcol = tid & 31, trow = tid >> 5;
    int row0 = blockIdx.x * 64;
    float acc[8][4];
    #pragma unroll
    for (int i = 0; i < 8; i++){ acc[i][0]=0.f; acc[i][1]=0.f; acc[i][2]=0.f; acc[i][3]=0.f; }

    for (int k0 = 0; k0 < 128; k0 += 16){
        #pragma unroll
        for (int i = 0; i < 4; i++){
            int lin = tid + 256*i;
            int r = lin >> 4, k = lin & 15;
            int gr = row0 + r;
            As[r*17+k] = (gr < Nn) ? g_h[(size_t)gr*Hh + k0 + k] : 0.f;
        }
        #pragma unroll
        for (int i = 0; i < 8; i++){
            int lin = tid + 256*i;
            int k = lin >> 7, c = lin & 127;
            Bs[k*128+c] = Wm1[(size_t)(k0+k)*128 + c];
        }
        __syncthreads();
        #pragma unroll
        for (int k = 0; k < 16; k++){
            float4 bv = *(const float4*)&Bs[k*128 + tcol*4];
            #pragma unroll
            for (int ri = 0; ri < 8; ri++){
                float a = As[(trow*8+ri)*17 + k];
                acc[ri][0] += a*bv.x; acc[ri][1] += a*bv.y;
                acc[ri][2] += a*bv.z; acc[ri][3] += a*bv.w;
            }
        }
        __syncthreads();
    }
    float4 b1v = *(const float4*)&bm1[tcol*4];
    #pragma unroll
    for (int ri = 0; ri < 8; ri++){
        float v0 = acc[ri][0]+b1v.x, v1 = acc[ri][1]+b1v.y;
        float v2 = acc[ri][2]+b1v.z, v3 = acc[ri][3]+b1v.w;
        float s1 = wsum(v0+v1+v2+v3);
        float s2 = wsum(v0*v0+v1*v1+v2*v2+v3*v3);
        float m  = s1 * (1.f/128.f);
        float var = s2 * (1.f/128.f) - m*m;
        float rs = rsqrtf(var + 1e-5f);
        int r = trow*8 + ri;
        float4 z = make_float4(fmaxf(0.f,(v0-m)*rs), fmaxf(0.f,(v1-m)*rs),
                               fmaxf(0.f,(v2-m)*rs), fmaxf(0.f,(v3-m)*rs));
        *(float4*)&Zs[r*132 + tcol*4] = z;
    }
    __syncthreads();

    float acc2[8][4];
    #pragma unroll
    for (int i = 0; i < 8; i++){ acc2[i][0]=0.f; acc2[i][1]=0.f; acc2[i][2]=0.f; acc2[i][3]=0.f; }
    for (int k0 = 0; k0 < 128; k0 += 16){
        #pragma unroll
        for (int i = 0; i < 8; i++){
            int lin = tid + 256*i;
            int k = lin >> 7, c = lin & 127;
            Bs[k*128+c] = Wm2[(size_t)(k0+k)*128 + c];
        }
        __syncthreads();
        #pragma unroll
        for (int k = 0; k < 16; k++){
            float4 bv = *(const float4*)&Bs[k*128 + tcol*4];
            #pragma unroll
            for (int ri = 0; ri < 8; ri++){
                float a = Zs[(trow*8+ri)*132 + k0 + k];
                acc2[ri][0] += a*bv.x; acc2[ri][1] += a*bv.y;
                acc2[ri][2] += a*bv.z; acc2[ri][3] += a*bv.w;
            }
        }
        __syncthreads();
    }
    float4 b2v = *(const float4*)&bm2[tcol*4];
    #pragma unroll
    for (int ri = 0; ri < 8; ri++){
        int gr = row0 + trow*8 + ri;
        float v0 = acc2[ri][0]+b2v.x, v1 = acc2[ri][1]+b2v.y;
        float v2 = acc2[ri][2]+b2v.z, v3 = acc2[ri][3]+b2v.w;
        float s1 = wsum(v0+v1+v2+v3);
        float s2 = wsum(v0*v0+v1*v1+v2*v2+v3*v3);
        float m  = s1 * (1.f/128.f);
        float varu = (s2 - 128.f*m*m) * (1.f/127.f);
        float sd = sqrtf(varu);
        float o0 = n2n((v0-m)/sd), o1 = n2n((v1-m)/sd);
        float o2 = n2n((v2-m)/sd), o3 = n2n((v3-m)/sd);
        if (gr < Nn){
            *(float4*)&g_xa[(size_t)gr*Hh + tcol*4] = make_float4(o0,o1,o2,o3);
            __half2 p0 = __floats2half2_rn(o0, o1);
            __half2 p1 = __floats2half2_rn(o2, o3);
            uint2 pw;
            pw.x = *(unsigned*)&p0; pw.y = *(unsigned*)&p1;
            *(uint2*)&g_xh[(size_t)gr*Hh + tcol*4] = pw;
        }
    }
}

// ---------------- mirror descent (inside grid barrier; fast-math exp) ----------------
__device__ void dev_md(int kiter){
    float w[Rr]; float l1 = 0.f;
    #pragma unroll
    for (int r = 0; r < Rr; r++){
        double nv = *(volatile double*)&g_node[r];
        double ev = *(volatile double*)&g_edge[r];
        w[r] = (float)((nv - ev) / (double)Nn);
        l1 += fabsf(w[r]);
        *(volatile double*)&g_node[r] = 0.0;
        *(volatile double*)&g_edge[r] = 0.0;
    }
    float clt;
    if (kiter == 0){ clt = l1; *(volatile float*)&g_clt = l1; }
    else clt = *(volatile float*)&g_clt;
    float u[Rr];
    #pragma unroll
    for (int r = 0; r < Rr; r++) u[r] = *(volatile float*)&g_u[r];
    float fi = l1 + 3.0f;          // ratio = 2*L2/L1 = 3
    const float tln = 2.f*1.6094379124341003f;   // 2*log(5)
    float inv_fi2 = 1.f/(fi*fi);
    bool ia = true;
    for (int t = 1; t <= 20 && ia; t++){
        float Tt = sqrtf(tln * inv_fi2 / (float)t);
        float uta[Rr]; float s = 0.f;
        #pragma unroll
        for (int r = 0; r < Rr; r++){ uta[r] = u[r]*__expf(-Tt*(3.f*u[r] + w[r])); s += uta[r]; }
        float is = 1.f/s;
        float dif = 0.f;
        #pragma unroll
        for (int r = 0; r < Rr; r++){
            uta[r] *= is;
            float d = u[r] - uta[r];
            dif += d*d;
            u[r] = uta[r];
        }
        ia = (dif >= 1e-6f);
    }
    #pragma unroll
    for (int r = 0; r < Rr; r++) *(volatile float*)&g_u[r] = u[r];
    int still = (l1 / clt >= 0.3f) ? 1 : 0;
    *(volatile int*)&g_still = still;
    *(volatile int*)&g_act   = still;
}

// ---------------- grid barrier (sense-reversing); last block may run md ----------------
__device__ __forceinline__ void gbar(int run_md, int kiter){
    __syncthreads();
    if (threadIdx.x == 0){
        unsigned s = g_bsense;
        __threadfence();
        unsigned a = atomicAdd(&g_bcount, 1u);
        if (a == (unsigned)(GRID - 1)){
            if (run_md) dev_md(kiter);
            g_bcount = 0u;
            __threadfence();
            g_bsense = s ^ 1u;
        } else {
            while (g_bsense == s) __nanosleep(64);
            __threadfence();
        }
    }
    __syncthreads();
}

// helper: fp16 row fetch (L2-only, cross-SM coherent) -> 4 floats
__device__ __forceinline__ void ld_row_cg(const __half* __restrict__ xh, int node, int lane,
                                          float& a, float& b, float& c, float& d){
    unsigned long long rv = __ldcg((const unsigned long long*)(xh + (size_t)node*Hh + lane*4));
    unsigned lo = (unsigned)rv, hi = (unsigned)(rv >> 32);
    float2 f0 = __half22float2(*(__half2*)&lo);
    float2 f1 = __half22float2(*(__half2*)&hi);
    a = f0.x; b = f0.y; c = f1.x; d = f1.y;
}

// ---------------- persistent loop: 8 x (gather -> md -> combine) + final output ----------------
__global__ void __launch_bounds__(BLK, 4) k_loop(const float* __restrict__ Wout,
                                                 const float* __restrict__ bout,
                                                 float* __restrict__ out, int out_size){
    __shared__ double sE[Rr], sN[Rr];
    __shared__ float  su[Rr];
    __shared__ float  swt[Hh*Cc];
    __shared__ float  sbv[Cc];
    int tid  = threadIdx.x;
    int lane = tid & 31;
    int gwarp = blockIdx.x*WPB + (tid >> 5);

    for (int k = 0; k < 8; k++){
        int act = *(volatile int*)&g_act;
        if (act){
            if (tid < Rr){ sE[tid] = 0.0; sN[tid] = 0.0; }
            __syncthreads();
            for (int n = gwarp; n < Nn; n += NWARPS){
                float x0, x1, x2, x3;
                {   // own row: written by this same warp last combine -> L1-safe
                    uint2 rv = *(const uint2*)(g_xh + (size_t)n*Hh + lane*4);
                    float2 f0 = __half22float2(*(const __half2*)&rv.x);
                    float2 f1 = __half22float2(*(const __half2*)&rv.y);
                    x0 = f0.x; x1 = f0.y; x2 = f1.x; x3 = f1.y;
                }
                float sq = wsum(x0*x0 + x1*x1 + x2*x2 + x3*x3);
                int e = g_rowptr[n];
                #pragma unroll
                for (int r = 0; r < Rr; r++){
                    int len = g_degi[r*Nn + n];
                    if (len > 0){
                        float m0=0.f, m1=0.f, m2=0.f, m3=0.f, dt=0.f;
                        int e1 = e + len;
                        for (; e + 4 <= e1; e += 4){
                            int2 c0p = g_csr[e],   c1p = g_csr[e+1];
                            int2 c2p = g_csr[e+2], c3p = g_csr[e+3];
                            float a0,a1,a2,a3, b0,b1,b2,b3, c0,c1,c2,c3, q0,q1,q2,q3;
                            ld_row_cg(g_xh, c0p.x, lane, a0,a1,a2,a3);
                            ld_row_cg(g_xh, c1p.x, lane, b0,b1,b2,b3);
                            ld_row_cg(g_xh, c2p.x, lane, c0,c1,c2,c3);
                            ld_row_cg(g_xh, c3p.x, lane, q0,q1,q2,q3);
                            m0 += a0+b0+c0+q0; m1 += a1+b1+c1+q1;
                            m2 += a2+b2+c2+q2; m3 += a3+b3+c3+q3;
                            dt += __int_as_float(c0p.y)*(x0*a0 + x1*a1 + x2*a2 + x3*a3);
                            dt += __int_as_float(c1p.y)*(x0*b0 + x1*b1 + x2*b2 + x3*b3);
                            dt += __int_as_float(c2p.y)*(x0*c0 + x1*c1 + x2*c2 + x3*c3);
                            dt += __int_as_float(c3p.y)*(x0*q0 + x1*q1 + x2*q2 + x3*q3);
                        }
                        for (; e < e1; e++){
                            int2 cp = g_csr[e];
                            float a0,a1,a2,a3;
                            ld_row_cg(g_xh, cp.x, lane, a0,a1,a2,a3);
                            m0 += a0; m1 += a1; m2 += a2; m3 += a3;
                            dt += __int_as_float(cp.y)*(x0*a0 + x1*a1 + x2*a2 + x3*a3);
                        }
                        float inv = 1.f/(float)len;
                        __half2 p0 = __floats2half2_rn(m0*inv, m1*inv);
                        __half2 p1 = __floats2half2_rn(m2*inv, m3*inv);
                        uint2 pw; pw.x = *(unsigned*)&p0; pw.y = *(unsigned*)&p1;
                        *(uint2*)(g_msgh + ((size_t)r*Nn + n)*Hh + lane*4) = pw;
                        dt = wsum(dt);
                        if (lane == 0){
                            atomicAdd(&sE[r], (double)dt);
                            atomicAdd(&sN[r], (double)sq);
                        }
                    }
                }
            }
            __syncthreads();
            if (tid < Rr){
                if (sE[tid] != 0.0) atomicAdd(&g_edge[tid], sE[tid]);
                if (sN[tid] != 0.0) atomicAdd(&g_node[tid], sN[tid]);
            }
        }
        gbar(act, k);                       // last-arriving block runs mirror descent

        int still = *(volatile int*)&g_still;
        if (still){
            if (tid < Rr) su[tid] = *(volatile float*)&g_u[tid];
            __syncthreads();
            const float c1 = 1.f/21.f, c2 = 20.f/21.f;
            for (int n = gwarp; n < Nn; n += NWARPS){
                float4 xv = *(const float4*)(g_xa + (size_t)n*Hh + lane*4);
                float a0=0.f, a1=0.f, a2=0.f, a3=0.f;
                #pragma unroll
                for (int r = 0; r < Rr; r++){
                    if (g_degi[r*Nn + n] > 0){
                        uint2 rv = *(const uint2*)(g_msgh + ((size_t)r*Nn + n)*Hh + lane*4);
                        float2 f0 = __half22float2(*(const __half2*)&rv.x);
                        float2 f1 = __half22float2(*(const __half2*)&rv.y);
                        float ur = su[r];
                        a0 += ur*f0.x; a1 += ur*f0.y; a2 += ur*f1.x; a3 += ur*f1.y;
                    }
                }
                float4 o = make_float4(xv.x*c1 + c2*a0, xv.y*c1 + c2*a1,
                                       xv.z*c1 + c2*a2, xv.w*c1 + c2*a3);
                *(float4*)(g_xa + (size_t)n*Hh + lane*4) = o;
                __half2 p0 = __floats2half2_rn(o.x, o.y);
                __half2 p1 = __floats2half2_rn(o.z, o.w);
                uint2 pw; pw.x = *(unsigned*)&p0; pw.y = *(unsigned*)&p1;
                *(uint2*)(g_xh + (size_t)n*Hh + lane*4) = pw;
            }
        }
        gbar(0, 0);
    }

    // ---------- final: logits + output packing ----------
    for (int i = tid; i < Hh*Cc; i += BLK) swt[i] = Wout[i];
    if (tid < Cc) sbv[tid] = bout[tid];
    __syncthreads();
    bool full = (out_size >= OFF_U + Rr);
    for (int n = gwarp; n < Nn; n += NWARPS){
        float4 xv = *(const float4*)(g_xa + (size_t)n*Hh + lane*4);
        if (full) *(float4*)(out + OFF_X + (size_t)n*Hh + lane*4) = xv;
        float xs[4] = {xv.x, xv.y, xv.z, xv.w};
        float acc[Cc];
        #pragma unroll
        for (int c = 0; c < Cc; c++) acc[c] = 0.f;
        #pragma unroll
        for (int i = 0; i < 4; i++){
            const float* wr = &swt[(lane*4 + i)*Cc];
            #pragma unroll
            for (int c = 0; c < Cc; c++) acc[c] += xs[i]*wr[c];
        }
        #pragma unroll
        for (int c = 0; c < Cc; c++) acc[c] = wsum(acc[c]);
        if (lane == 0){
            #pragma unroll
            for (int c = 0; c < Cc; c++) out[(size_t)n*Cc + c] = acc[c] + sbv[c];
        }
    }
    if (full && blockIdx.x == 0 && tid < Rr) out[OFF_U + tid] = *(volatile float*)&g_u[tid];
}

// ---------------- host launcher ----------------
extern "C" void kernel_launch(void* const* d_in, const int* in_sizes, int n_in,
                              void* d_out, int out_size){
    const float* feat0 = (const float*)d_in[0];
    const float* feat1 = (const float*)d_in[1];
    const float* W0   = (const float*)d_in[2];  const float* b0   = (const float*)d_in[3];
    const float* W1   = (const float*)d_in[4];  const float* b1   = (const float*)d_in[5];
    const float* Wm1  = (const float*)d_in[6];  const float* bm1  = (const float*)d_in[7];
    const float* Wm2  = (const float*)d_in[8];  const float* bm2  = (const float*)d_in[9];
    const float* Wout = (const float*)d_in[10]; const float* bout = (const float*)d_in[11];
    const int*   src  = (const int*)d_in[12];
    const int*   dst  = (const int*)d_in[13];
    const int*   rel  = (const int*)d_in[14];
    float* out = (float*)d_out;

    const int EB = (Ee + 255)/256;          // 2344
    const int NB_SCAN = (Nn + 1023)/1024;   // 30

    // fork-join resources created once, on the first (non-captured) call
    static cudaStream_t s2 = nullptr;
    static cudaEvent_t evFork = nullptr, evJoin = nullptr;
    if (s2 == nullptr){
        cudaStreamCreateWithFlags(&s2, cudaStreamNonBlocking);
        cudaEventCreateWithFlags(&evFork, cudaEventDisableTiming);
        cudaEventCreateWithFlags(&evJoin, cudaEventDisableTiming);
    }

    k_init<<<256, 256>>>();

    // fork: graph-prep chain on s2, MLP chain on the launch stream
    cudaEventRecord(evFork, 0);
    cudaStreamWaitEvent(s2, evFork, 0);

    k_count<<<EB, 256, 0, s2>>>(src, rel);
    k_scan1<<<NB_SCAN, 1024, 0, s2>>>();
    k_scan2<<<1, 32, 0, s2>>>(NB_SCAN);
    k_scan3c<<<(Nn+255)/256, 256, 0, s2>>>();
    k_scatter2<<<EB, 256, 0, s2>>>(src, dst, rel);
    cudaEventRecord(evJoin, s2);

    k_typed<<<NB0 + NB1, 256>>>(feat0, W0, b0, feat1, W1, b1);   // 470 blocks
    k_mlp2<<<(Nn+63)/64, 256>>>(Wm1, bm1, Wm2, bm2);             // 469 blocks

    // join
    cudaStreamWaitEvent(0, evJoin, 0);

    k_loop<<<GRID, BLK>>>(Wout, bout, out, out_size);
}

// round 16
// speedup vs baseline: 1.2903x; 1.0143x over previous
#include <cuda_runtime.h>
#include <cuda_fp16.h>
#include <math.h>

#define Nn 30000
#define NN0 18000
#define NN1 12000
#define Rr 5
#define Ee 600000
#define Hh 128
#define Cc 8
#define OFF_X (Nn*Cc)            /* 240000   */
#define OFF_U (OFF_X + Nn*Hh)    /* 4080000  */

#define GRID 592                  /* 148 SMs x 4 co-resident blocks */
#define BLK  256
#define WPB  (BLK/32)
#define NWARPS (GRID*WPB)

#define NB0 ((NN0+63)/64)         /* 282 */
#define NB1 ((NN1+63)/64)         /* 188 */

// ---------------- device scratch (static, no allocation) ----------------
__device__ float  g_h [Nn*Hh];
__device__ __half g_xh[Nn*Hh];                 // fp16 x (single copy, updated in place)
__device__ __half g_msgh[(size_t)Rr*Nn*Hh];    // per-relation messages fp16
__device__ int    g_degi[Rr*Nn];
__device__ int    g_cnt[Nn];
__device__ int    g_rowptr[Nn+1];
__device__ int    g_cur2[Rr*Nn];
__device__ int    g_bsums[64];
__device__ int2   g_csr[Ee];                   // (dst, edinv-as-int) packed
__device__ double g_node[Rr];
__device__ double g_edge[Rr];
__device__ float  g_u[Rr];
__device__ float  g_clt;
__device__ int    g_act;
__device__ int    g_still;
__device__ unsigned g_bcount;
__device__ volatile unsigned g_bsense;

__device__ __forceinline__ float wsum(float v){
    #pragma unroll
    for (int o = 16; o; o >>= 1) v += __shfl_xor_sync(0xffffffffu, v, o);
    return v;
}
__device__ __forceinline__ float n2n(float v){
    if (isnan(v)) return 0.f;
    if (isinf(v)) return v > 0.f ? 3.4028234663852886e38f : -3.4028234663852886e38f;
    return v;
}

// ---------------- init / graph preprocessing ----------------
__global__ void k_init(){
    int i = blockIdx.x*blockDim.x + threadIdx.x;
    int st = gridDim.x*blockDim.x;
    for (int j = i; j < Rr*Nn; j += st) g_degi[j] = 0;
    for (int j = i; j < Nn;    j += st) g_cnt[j]  = 0;
    if (i < Rr) { g_node[i] = 0.0; g_edge[i] = 0.0; g_u[i] = 0.2f; }
    if (i == 0) { g_act = 1; g_still = 1; g_bcount = 0u; g_bsense = 0u; }
}

__global__ void k_count(const int* __restrict__ src, const int* __restrict__ rel){
    int i = blockIdx.x*blockDim.x + threadIdx.x;
    if (i < Ee) {
        atomicAdd(&g_degi[rel[i]*Nn + src[i]], 1);
        atomicAdd(&g_cnt[src[i]], 1);
    }
}

__global__ void k_scan1(){
    __shared__ int s[1024];
    int i = blockIdx.x*1024 + threadIdx.x;
    int v = (i < Nn) ? g_cnt[i] : 0;
    s[threadIdx.x] = v;
    __syncthreads();
    for (int off = 1; off < 1024; off <<= 1){
        int t = 0;
        if (threadIdx.x >= off) t = s[threadIdx.x - off];
        __syncthreads();
        if (threadIdx.x >= off) s[threadIdx.x] += t;
        __syncthreads();
    }
    if (i < Nn) g_rowptr[i] = s[threadIdx.x] - v;
    if (threadIdx.x == 1023) g_bsums[blockIdx.x] = s[1023];
}

__global__ void k_scan2(int nb){
    if (threadIdx.x == 0){
        int run = 0;
        for (int b = 0; b < nb; b++){ int t = g_bsums[b]; g_bsums[b] = run; run += t; }
    }
}

// fused: finalize rowptr + per-(node,rel) cursors
__global__ void k_scan3c(){
    int i = blockIdx.x*blockDim.x + threadIdx.x;
    if (i < Nn){
        int base = g_rowptr[i] + g_bsums[i >> 10];
        g_rowptr[i] = base;
        #pragma unroll
        for (int r = 0; r < Rr; r++){
            g_cur2[r*Nn + i] = base;
            base += g_degi[r*Nn + i];
        }
    }
    if (i == 0) g_rowptr[Nn] = Ee;
}

__global__ void k_scatter2(const int* __restrict__ src, const int* __restrict__ dst,
                           const int* __restrict__ rel){
    int i = blockIdx.x*blockDim.x + threadIdx.x;
    if (i >= Ee) return;
    int s = src[i], r = rel[i], d = dst[i];
    int pos = atomicAdd(&g_cur2[r*Nn + s], 1);
    int degs = g_degi[r*Nn + s];
    int degd = g_degi[r*Nn + d];
    float ei = (1.f/sqrtf((float)degs)) * (degd > 0 ? 1.f/sqrtf((float)degd) : 0.f);
    int2 pk; pk.x = d; pk.y = __float_as_int(ei);
    g_csr[pos] = pk;
}

// ------- merged typed GEMM: blocks [0,NB0) do feat0@W0, [NB0,NB0+NB1) do feat1@W1 -------
__global__ void __launch_bounds__(256, 2) k_typed(const float* __restrict__ feat0,
                                                  const float* __restrict__ W0,
                                                  const float* __restrict__ b0,
                                                  const float* __restrict__ feat1,
                                                  const float* __restrict__ W1,
                                                  const float* __restrict__ b1){
    __shared__ float As[64*17];
    __shared__ float Bs[16*128];
    const float *A, *W, *bias;
    int lda, nrows, rowbase, K, blk;
    if (blockIdx.x < NB0){
        A = feat0; W = W0; bias = b0; lda = 256; nrows = NN0; rowbase = 0;   K = 256; blk = blockIdx.x;
    } else {
        A = feat1; W = W1; bias = b1; lda = 128; nrows = NN1; rowbase = NN0; K = 128; blk = blockIdx.x - NB0;
    }
    int tid  = threadIdx.x;
    int tcol = tid & 31, trow = tid >> 5;
    int row0 = blk * 64;
    float acc[8][4];
    #pragma unroll
    for (int i = 0; i < 8; i++){ acc[i][0]=0.f; acc[i][1]=0.f; acc[i][2]=0.f; acc[i][3]=0.f; }

    for (int k0 = 0; k0 < K; k0 += 16){
        #pragma unroll
        for (int i = 0; i < 4; i++){
            int lin = tid + 256*i;
            int r = lin >> 4, k = lin & 15;
            int gr = row0 + r;
            As[r*17+k] = (gr < nrows) ? A[(size_t)gr*lda + k0 + k] : 0.f;
        }
        #pragma unroll
        for (int i = 0; i < 8; i++){
            int lin = tid + 256*i;
            int k = lin >> 7, c = lin & 127;
            Bs[k*128+c] = W[(size_t)(k0+k)*128 + c];
        }
        __syncthreads();
        #pragma unroll
        for (int k = 0; k < 16; k++){
            float4 bv = *(const float4*)&Bs[k*128 + tcol*4];
            #pragma unroll
            for (int ri = 0; ri < 8; ri++){
                float a = As[(trow*8+ri)*17 + k];
                acc[ri][0] += a*bv.x; acc[ri][1] += a*bv.y;
                acc[ri][2] += a*bv.z; acc[ri][3] += a*bv.w;
            }
        }
        __syncthreads();
    }
    float4 bv = *(const float4*)&bias[tcol*4];
    #pragma unroll
    for (int ri = 0; ri < 8; ri++){
        int gr = row0 + trow*8 + ri;
        if (gr < nrows){
            float4 o = make_float4(acc[ri][0]+bv.x, acc[ri][1]+bv.y,
                                   acc[ri][2]+bv.z, acc[ri][3]+bv.w);
            *(float4*)&g_h[(size_t)(rowbase+gr)*Hh + tcol*4] = o;
        }
    }
}

// ---------------- stage B: LN(h@Wm1+b)->relu -> @Wm2+b -> standardize ----------------
__global__ void __launch_bounds__(256, 2) k_mlp2(const float* __restrict__ Wm1, const float* __restrict__ bm1,
                                                 const float* __restrict__ Wm2, const float* __restrict__ bm2){
    __shared__ float As[64*17];
    __shared__ float Bs[16*128];
    __shared__ float Zs[64*132];
    int tid  = threadIdx.x;
    int tcol = tid & 31, trow = tid >> 5;
    int row0 = blockIdx.x * 64;
    float acc[8][4];
    #pragma unroll
    for (int i = 0; i < 8; i++){ acc[i][0]=0.f; acc[i][1]=0.f; acc[i][2]=0.f; acc[i][3]=0.f; }

    for (int k0 = 0; k0 < 128; k0 += 16){
        #pragma unroll
        for (int i = 0; i < 4; i++){
            int lin = tid + 256*i;
            int r = lin >> 4, k = lin & 15;
            int gr = row0 + r;
            As[r*17+k] = (gr < Nn) ? g_h[(size_t)gr*Hh + k0 + k] : 0.f;
        }
        #pragma unroll
        for (int i = 0; i < 8; i++){
            int lin = tid + 256*i;
            int k = lin >> 7, c = lin & 127;
            Bs[k*128+c] = Wm1[(size_t)(k0+k)*128 + c];
        }
        __syncthreads();
        #pragma unroll
        for (int k = 0; k < 16; k++){
            float4 bv = *(const float4*)&Bs[k*128 + tcol*4];
            #pragma unroll
            for (int ri = 0; ri < 8; ri++){
                float a = As[(trow*8+ri)*17 + k];
                acc[ri][0] += a*bv.x; acc[ri][1] += a*bv.y;
                acc[ri][2] += a*bv.z; acc[ri][3] += a*bv.w;
            }
        }
        __syncthreads();
    }
    float4 b1v = *(const float4*)&bm1[tcol*4];
    #pragma unroll
    for (int ri = 0; ri < 8; ri++){
        float v0 = acc[ri][0]+b1v.x, v1 = acc[ri][1]+b1v.y;
        float v2 = acc[ri][2]+b1v.z, v3 = acc[ri][3]+b1v.w;
        float s1 = wsum(v0+v1+v2+v3);
        float s2 = wsum(v0*v0+v1*v1+v2*v2+v3*v3);
        float m  = s1 * (1.f/128.f);
        float var = s2 * (1.f/128.f) - m*m;
        float rs = rsqrtf(var + 1e-5f);
        int r = trow*8 + ri;
        float4 z = make_float4(fmaxf(0.f,(v0-m)*rs), fmaxf(0.f,(v1-m)*rs),
                               fmaxf(0.f,(v2-m)*rs), fmaxf(0.f,(v3-m)*rs));
        *(float4*)&Zs[r*132 + tcol*4] = z;
    }
    __syncthreads();

    float acc2[8][4];
    #pragma unroll
    for (int i = 0; i < 8; i++){ acc2[i][0]=0.f; acc2[i][1]=0.f; acc2[i][2]=0.f; acc2[i][3]=0.f; }
    for (int k0 = 0; k0 < 128; k0 += 16){
        #pragma unroll
        for (int i = 0; i < 8; i++){
            int lin = tid + 256*i;
            int k = lin >> 7, c = lin & 127;
            Bs[k*128+c] = Wm2[(size_t)(k0+k)*128 + c];
        }
        __syncthreads();
        #pragma unroll
        for (int k = 0; k < 16; k++){
            float4 bv = *(const float4*)&Bs[k*128 + tcol*4];
            #pragma unroll
            for (int ri = 0; ri < 8; ri++){
                float a = Zs[(trow*8+ri)*132 + k0 + k];
                acc2[ri][0] += a*bv.x; acc2[ri][1] += a*bv.y;
                acc2[ri][2] += a*bv.z; acc2[ri][3] += a*bv.w;
            }
        }
        __syncthreads();
    }
    float4 b2v = *(const float4*)&bm2[tcol*4];
    #pragma unroll
    for (int ri = 0; ri < 8; ri++){
        int gr = row0 + trow*8 + ri;
        float v0 = acc2[ri][0]+b2v.x, v1 = acc2[ri][1]+b2v.y;
        float v2 = acc2[ri][2]+b2v.z, v3 = acc2[ri][3]+b2v.w;
        float s1 = wsum(v0+v1+v2+v3);
        float s2 = wsum(v0*v0+v1*v1+v2*v2+v3*v3);
        float m  = s1 * (1.f/128.f);
        float varu = (s2 - 128.f*m*m) * (1.f/127.f);
        float sd = sqrtf(varu);
        float o0 = n2n((v0-m)/sd), o1 = n2n((v1-m)/sd);
        float o2 = n2n((v2-m)/sd), o3 = n2n((v3-m)/sd);
        if (gr < Nn){
            __half2 p0 = __floats2half2_rn(o0, o1);
            __half2 p1 = __floats2half2_rn(o2, o3);
            uint2 pw;
            pw.x = *(unsigned*)&p0; pw.y = *(unsigned*)&p1;
            *(uint2*)&g_xh[(size_t)gr*Hh + tcol*4] = pw;
        }
    }
}

// ---------------- mirror descent (inside grid barrier; fast-math exp) ----------------
__device__ void dev_md(int kiter){
    float w[Rr]; float l1 = 0.f;
    #pragma unroll
    for (int r = 0; r < Rr; r++){
        double nv = *(volatile double*)&g_node[r];
        double ev = *(volatile double*)&g_edge[r];
        w[r] = (float)((nv - ev) / (double)Nn);
        l1 += fabsf(w[r]);
        *(volatile double*)&g_node[r] = 0.0;
        *(volatile double*)&g_edge[r] = 0.0;
    }
    float clt;
    if (kiter == 0){ clt = l1; *(volatile float*)&g_clt = l1; }
    else clt = *(volatile float*)&g_clt;
    float u[Rr];
    #pragma unroll
    for (int r = 0; r < Rr; r++) u[r] = *(volatile float*)&g_u[r];
    float fi = l1 + 3.0f;          // ratio = 2*L2/L1 = 3
    const float tln = 2.f*1.6094379124341003f;   // 2*log(5)
    float inv_fi2 = 1.f/(fi*fi);
    bool ia = true;
    for (int t = 1; t <= 20 && ia; t++){
        float Tt = sqrtf(tln * inv_fi2 / (float)t);
        float uta[Rr]; float s = 0.f;
        #pragma unroll
        for (int r = 0; r < Rr; r++){ uta[r] = u[r]*__expf(-Tt*(3.f*u[r] + w[r])); s += uta[r]; }
        float is = 1.f/s;
        float dif = 0.f;
        #pragma unroll
        for (int r = 0; r < Rr; r++){
            uta[r] *= is;
            float d = u[r] - uta[r];
            dif += d*d;
            u[r] = uta[r];
        }
        ia = (dif >= 1e-6f);
    }
    #pragma unroll
    for (int r = 0; r < Rr; r++) *(volatile float*)&g_u[r] = u[r];
    int still = (l1 / clt >= 0.3f) ? 1 : 0;
    *(volatile int*)&g_still = still;
    *(volatile int*)&g_act   = still;
}

// ---------------- grid barrier (sense-reversing); last block may run md ----------------
__device__ __forceinline__ void gbar(int run_md, int kiter){
    __syncthreads();
    if (threadIdx.x == 0){
        unsigned s = g_bsense;
        __threadfence();
        unsigned a = atomicAdd(&g_bcount, 1u);
        if (a == (unsigned)(GRID - 1)){
            if (run_md) dev_md(kiter);
            g_bcount = 0u;
            __threadfence();
            g_bsense = s ^ 1u;
        } else {
            while (g_bsense == s) __nanosleep(64);
            __threadfence();
        }
    }
    __syncthreads();
}

// helper: fp16 row fetch (L2-only, cross-SM coherent) -> 4 floats
__device__ __forceinline__ void ld_row_cg(const __half* __restrict__ xh, int node, int lane,
                                          float& a, float& b, float& c, float& d){
    unsigned long long rv = __ldcg((const unsigned long long*)(xh + (size_t)node*Hh + lane*4));
    unsigned lo = (unsigned)rv, hi = (unsigned)(rv >> 32);
    float2 f0 = __half22float2(*(__half2*)&lo);
    float2 f1 = __half22float2(*(__half2*)&hi);
    a = f0.x; b = f0.y; c = f1.x; d = f1.y;
}

// ---------------- persistent loop: 8 x (gather -> md -> combine) + final output ----------------
__global__ void __launch_bounds__(BLK, 4) k_loop(const float* __restrict__ Wout,
                                                 const float* __restrict__ bout,
                                                 float* __restrict__ out, int out_size){
    __shared__ double sE[Rr], sN[Rr];
    __shared__ float  su[Rr];
    __shared__ float  swt[Hh*Cc];
    __shared__ float  sbv[Cc];
    int tid  = threadIdx.x;
    int lane = tid & 31;
    int gwarp = blockIdx.x*WPB + (tid >> 5);

    for (int k = 0; k < 8; k++){
        int act = *(volatile int*)&g_act;
        if (act){
            if (tid < Rr){ sE[tid] = 0.0; sN[tid] = 0.0; }
            __syncthreads();
            for (int n = gwarp; n < Nn; n += NWARPS){
                float x0, x1, x2, x3;
                {   // own row: written by this same warp last combine -> L1-safe
                    uint2 rv = *(const uint2*)(g_xh + (size_t)n*Hh + lane*4);
                    float2 f0 = __half22float2(*(const __half2*)&rv.x);
                    float2 f1 = __half22float2(*(const __half2*)&rv.y);
                    x0 = f0.x; x1 = f0.y; x2 = f1.x; x3 = f1.y;
                }
                float sq = wsum(x0*x0 + x1*x1 + x2*x2 + x3*x3);
                int e = g_rowptr[n];
                #pragma unroll
                for (int r = 0; r < Rr; r++){
                    int len = g_degi[r*Nn + n];
                    if (len > 0){
                        float m0=0.f, m1=0.f, m2=0.f, m3=0.f, dt=0.f;
                        int e1 = e + len;
                        for (; e + 4 <= e1; e += 4){
                            int2 c0p = g_csr[e],   c1p = g_csr[e+1];
                            int2 c2p = g_csr[e+2], c3p = g_csr[e+3];
                            float a0,a1,a2,a3, b0,b1,b2,b3, c0,c1,c2,c3, q0,q1,q2,q3;
                            ld_row_cg(g_xh, c0p.x, lane, a0,a1,a2,a3);
                            ld_row_cg(g_xh, c1p.x, lane, b0,b1,b2,b3);
                            ld_row_cg(g_xh, c2p.x, lane, c0,c1,c2,c3);
                            ld_row_cg(g_xh, c3p.x, lane, q0,q1,q2,q3);
                            m0 += a0+b0+c0+q0; m1 += a1+b1+c1+q1;
                            m2 += a2+b2+c2+q2; m3 += a3+b3+c3+q3;
                            dt += __int_as_float(c0p.y)*(x0*a0 + x1*a1 + x2*a2 + x3*a3);
                            dt += __int_as_float(c1p.y)*(x0*b0 + x1*b1 + x2*b2 + x3*b3);
                            dt += __int_as_float(c2p.y)*(x0*c0 + x1*c1 + x2*c2 + x3*c3);
                            dt += __int_as_float(c3p.y)*(x0*q0 + x1*q1 + x2*q2 + x3*q3);
                        }
                        for (; e < e1; e++){
                            int2 cp = g_csr[e];
                            float a0,a1,a2,a3;
                            ld_row_cg(g_xh, cp.x, lane, a0,a1,a2,a3);
                            m0 += a0; m1 += a1; m2 += a2; m3 += a3;
                            dt += __int_as_float(cp.y)*(x0*a0 + x1*a1 + x2*a2 + x3*a3);
                        }
                        float inv = 1.f/(float)len;
                        __half2 p0 = __floats2half2_rn(m0*inv, m1*inv);
                        __half2 p1 = __floats2half2_rn(m2*inv, m3*inv);
                        uint2 pw; pw.x = *(unsigned*)&p0; pw.y = *(unsigned*)&p1;
                        *(uint2*)(g_msgh + ((size_t)r*Nn + n)*Hh + lane*4) = pw;
                        dt = wsum(dt);
                        if (lane == 0){
                            atomicAdd(&sE[r], (double)dt);
                            atomicAdd(&sN[r], (double)sq);
                        }
                    }
                }
            }
            __syncthreads();
            if (tid < Rr){
                if (sE[tid] != 0.0) atomicAdd(&g_edge[tid], sE[tid]);
                if (sN[tid] != 0.0) atomicAdd(&g_node[tid], sN[tid]);
            }
        }
        gbar(act, k);                       // last-arriving block runs mirror descent

        int still = *(volatile int*)&g_still;
        if (still){
            if (tid < Rr) su[tid] = *(volatile float*)&g_u[tid];
            __syncthreads();
            const float c1 = 1.f/21.f, c2 = 20.f/21.f;
            for (int n = gwarp; n < Nn; n += NWARPS){
                float x0, x1, x2, x3;
                {   // own row (same warp wrote/read it) -> L1-safe
                    uint2 rv = *(const uint2*)(g_xh + (size_t)n*Hh + lane*4);
                    float2 f0 = __half22float2(*(const __half2*)&rv.x);
                    float2 f1 = __half22float2(*(const __half2*)&rv.y);
                    x0 = f0.x; x1 = f0.y; x2 = f1.x; x3 = f1.y;
                }
                float a0=0.f, a1=0.f, a2=0.f, a3=0.f;
                #pragma unroll
                for (int r = 0; r < Rr; r++){
                    if (g_degi[r*Nn + n] > 0){
                        uint2 rv = *(const uint2*)(g_msgh + ((size_t)r*Nn + n)*Hh + lane*4);
                        float2 f0 = __half22float2(*(const __half2*)&rv.x);
                        float2 f1 = __half22float2(*(const __half2*)&rv.y);
                        float ur = su[r];
                        a0 += ur*f0.x; a1 += ur*f0.y; a2 += ur*f1.x; a3 += ur*f1.y;
                    }
                }
                float o0 = x0*c1 + c2*a0, o1 = x1*c1 + c2*a1;
                float o2 = x2*c1 + c2*a2, o3 = x3*c1 + c2*a3;
                __half2 p0 = __floats2half2_rn(o0, o1);
                __half2 p1 = __floats2half2_rn(o2, o3);
                uint2 pw; pw.x = *(unsigned*)&p0; pw.y = *(unsigned*)&p1;
                *(uint2*)(g_xh + (size_t)n*Hh + lane*4) = pw;
            }
        }
        gbar(0, 0);
    }

    // ---------- final: logits + output packing (x read from fp16) ----------
    for (int i = tid; i < Hh*Cc; i += BLK) swt[i] = Wout[i];
    if (tid < Cc) sbv[tid] = bout[tid];
    __syncthreads();
    bool full = (out_size >= OFF_U + Rr);
    for (int n = gwarp; n < Nn; n += NWARPS){
        float xs[4];
        {
            uint2 rv = *(const uint2*)(g_xh + (size_t)n*Hh + lane*4);
            float2 f0 = __half22float2(*(const __half2*)&rv.x);
            float2 f1 = __half22float2(*(const __half2*)&rv.y);
            xs[0] = f0.x; xs[1] = f0.y; xs[2] = f1.x; xs[3] = f1.y;
        }
        if (full)
            *(float4*)(out + OFF_X + (size_t)n*Hh + lane*4) =
                make_float4(xs[0], xs[1], xs[2], xs[3]);
        float acc[Cc];
        #pragma unroll
        for (int c = 0; c < Cc; c++) acc[c] = 0.f;
        #pragma unroll
        for (int i = 0; i < 4; i++){
            const float* wr = &swt[(lane*4 + i)*Cc];
            #pragma unroll
            for (int c = 0; c < Cc; c++) acc[c] += xs[i]*wr[c];
        }
        #pragma unroll
        for (int c = 0; c < Cc; c++) acc[c] = wsum(acc[c]);
        if (lane == 0){
            #pragma unroll
            for (int c = 0; c < Cc; c++) out[(size_t)n*Cc + c] = acc[c] + sbv[c];
        }
    }
    if (full && blockIdx.x == 0 && tid < Rr) out[OFF_U + tid] = *(volatile float*)&g_u[tid];
}

// ---------------- host launcher ----------------
extern "C" void kernel_launch(void* const* d_in, const int* in_sizes, int n_in,
                              void* d_out, int out_size){
    const float* feat0 = (const float*)d_in[0];
    const float* feat1 = (const float*)d_in[1];
    const float* W0   = (const float*)d_in[2];  const float* b0   = (const float*)d_in[3];
    const float* W1   = (const float*)d_in[4];  const float* b1   = (const float*)d_in[5];
    const float* Wm1  = (const float*)d_in[6];  const float* bm1  = (const float*)d_in[7];
    const float* Wm2  = (const float*)d_in[8];  const float* bm2  = (const float*)d_in[9];
    const float* Wout = (const float*)d_in[10]; const float* bout = (const float*)d_in[11];
    const int*   src  = (const int*)d_in[12];
    const int*   dst  = (const int*)d_in[13];
    const int*   rel  = (const int*)d_in[14];
    float* out = (float*)d_out;

    const int EB = (Ee + 255)/256;          // 2344
    const int NB_SCAN = (Nn + 1023)/1024;   // 30

    // fork-join resources created once, on the first (non-captured) call
    static cudaStream_t s2 = nullptr;
    static cudaEvent_t evFork = nullptr, evJoin = nullptr;
    if (s2 == nullptr){
        cudaStreamCreateWithFlags(&s2, cudaStreamNonBlocking);
        cudaEventCreateWithFlags(&evFork, cudaEventDisableTiming);
        cudaEventCreateWithFlags(&evJoin, cudaEventDisableTiming);
    }

    k_init<<<256, 256>>>();

    // fork: graph-prep chain on s2, MLP chain on the launch stream
    cudaEventRecord(evFork, 0);
    cudaStreamWaitEvent(s2, evFork, 0);

    k_count<<<EB, 256, 0, s2>>>(src, rel);
    k_scan1<<<NB_SCAN, 1024, 0, s2>>>();
    k_scan2<<<1, 32, 0, s2>>>(NB_SCAN);
    k_scan3c<<<(Nn+255)/256, 256, 0, s2>>>();
    k_scatter2<<<EB, 256, 0, s2>>>(src, dst, rel);
    cudaEventRecord(evJoin, s2);

    k_typed<<<NB0 + NB1, 256>>>(feat0, W0, b0, feat1, W1, b1);   // 470 blocks
    k_mlp2<<<(Nn+63)/64, 256>>>(Wm1, bm1, Wm2, bm2);             // 469 blocks

    // join
    cudaStreamWaitEvent(0, evJoin, 0);

    k_loop<<<GRID, BLK>>>(Wout, bout, out, out_size);
}